// round 2
// baseline (speedup 1.0000x reference)
#include <cuda_runtime.h>
#include <cstdint>
#include <math.h>

#define Bdim 128
#define Tdim 32
#define Edim 512
#define Hdim 1024
#define G4   4096
#define Vdim 32000
#define NTILES 16

// ---------------- device scratch (no allocations allowed) ----------------
__device__ __align__(16) float g_X[Bdim * Tdim * Edim];        // 8 MB
__device__ __align__(16) float g_G0[Bdim * Tdim * G4];         // 64 MB
__device__ __align__(16) float g_ys[Bdim * Tdim * Hdim];       // 16 MB
__device__ __align__(16) float g_bias1[G4];
__device__ __align__(16) float g_hcat[2][Tdim * 2048];         // [par][t][h0|h1]
__device__ __align__(16) float g_c0[Tdim * Hdim];
__device__ __align__(16) float g_c1[Tdim * Hdim];
__device__ __align__(16) float g_W1cat[(size_t)G4 * 2048];     // [Wih1|Whh1] 32MB
__device__ __align__(16) float g_part0[4 * Tdim * G4];         // 2MB
__device__ __align__(16) float g_part1[8 * Tdim * G4];         // 4MB
__device__ int g_cnt0[NTILES];
__device__ int g_cnt1[NTILES];

// ---------------- helpers ----------------
__device__ __forceinline__ uint32_t f2tf(float x) {
    uint32_t r;
    asm("cvt.rna.tf32.f32 %0, %1;" : "=r"(r) : "f"(x));
    return r;
}

__device__ __forceinline__ void mma_tf32(float c[4], const uint32_t a[4], const uint32_t b[2]) {
    asm volatile(
        "mma.sync.aligned.m16n8k8.row.col.f32.tf32.tf32.f32 "
        "{%0,%1,%2,%3}, {%4,%5,%6,%7}, {%8,%9}, {%0,%1,%2,%3};"
        : "+f"(c[0]), "+f"(c[1]), "+f"(c[2]), "+f"(c[3])
        : "r"(a[0]), "r"(a[1]), "r"(a[2]), "r"(a[3]), "r"(b[0]), "r"(b[1]));
}

__device__ __forceinline__ void cp16(float* s, const float* g) {
    uint32_t sa = (uint32_t)__cvta_generic_to_shared(s);
    asm volatile("cp.async.cg.shared.global [%0], [%1], 16;" :: "r"(sa), "l"(g));
}
__device__ __forceinline__ void cp_commit() { asm volatile("cp.async.commit_group;" ::: "memory"); }

__device__ __forceinline__ float sigm(float x) { return 1.f / (1.f + expf(-x)); }

// ---------------- init ----------------
__global__ void init_kernel(const float* __restrict__ b_ih1, const float* __restrict__ b_hh1) {
    int i = blockIdx.x * blockDim.x + threadIdx.x;
    if (i < Tdim * 2048) { g_hcat[0][i] = 0.f; g_hcat[1][i] = 0.f; }
    if (i < Tdim * Hdim) { g_c0[i] = 0.f; g_c1[i] = 0.f; }
    if (i < G4) g_bias1[i] = b_ih1[i] + b_hh1[i];
    if (i < NTILES) { g_cnt0[i] = 0; g_cnt1[i] = 0; }
}

// ---------------- W1cat = [W_ih1 | W_hh1] : [4096][2048] ----------------
__global__ void make_w1cat(const float* __restrict__ Wi1, const float* __restrict__ Wh1) {
    size_t i = (size_t)blockIdx.x * 256 + threadIdx.x;   // float4 index, 2M total
    int n = (int)(i >> 9);       // 512 float4 per row
    int c4 = (int)(i & 511);
    const float4* src = (c4 < 256)
        ? reinterpret_cast<const float4*>(Wi1 + (size_t)n * Hdim) + c4
        : reinterpret_cast<const float4*>(Wh1 + (size_t)n * Hdim) + (c4 - 256);
    reinterpret_cast<float4*>(g_W1cat)[i] = *src;
}

// ---------------- build X: t==0 -> features, t>=1 -> embed ----------------
__global__ void build_x(const float* __restrict__ features, const int* __restrict__ captions,
                        const float* __restrict__ embW) {
    int b = blockIdx.x, t = blockIdx.y;
    const float* src = (t == 0) ? (features + (size_t)b * Edim)
                                : (embW + (size_t)captions[b * Tdim + t] * Edim);
    float4* dst = reinterpret_cast<float4*>(g_X + ((size_t)b * Tdim + t) * Edim);
    const float4* s4 = reinterpret_cast<const float4*>(src);
    dst[threadIdx.x] = s4[threadIdx.x];
}

// ---------------- big tf32 GEMM: C[M,N] = A[M,K] @ W[N,K]^T + bias ----------------
#define BM 128
#define BN 256
#define BKx 32
#define LDSS 36

__global__ void __launch_bounds__(256, 1) gemm_tf32(
    const float* __restrict__ A, const float* __restrict__ W,
    const float* __restrict__ bias0, const float* __restrict__ bias1,
    float* __restrict__ C, int M, int N, int K)
{
    extern __shared__ float smem_f[];
    float* As = smem_f;
    float* Bs = smem_f + 2 * BM * LDSS;

    int tid = threadIdx.x;
    int lane = tid & 31, warp = tid >> 5;
    int m0 = blockIdx.x * BM, n0 = blockIdx.y * BN;
    int wm = (warp >> 2) * 64, wn = (warp & 3) * 64;

    float acc[4][8][4];
    #pragma unroll
    for (int a = 0; a < 4; a++)
        #pragma unroll
        for (int b = 0; b < 8; b++)
            #pragma unroll
            for (int c = 0; c < 4; c++) acc[a][b][c] = 0.f;

    auto load_stage = [&](int s, int buf) {
        int k0 = s * BKx;
        const float* Ag = A + (size_t)m0 * K + k0;
        #pragma unroll
        for (int i = 0; i < 4; i++) {
            int idx = tid + i * 256;
            int m = idx >> 3, seg = idx & 7;
            cp16(&As[buf * BM * LDSS + m * LDSS + seg * 4], Ag + (size_t)m * K + seg * 4);
        }
        const float* Wg = W + (size_t)n0 * K + k0;
        #pragma unroll
        for (int i = 0; i < 8; i++) {
            int idx = tid + i * 256;
            int n = idx >> 3, seg = idx & 7;
            cp16(&Bs[buf * BN * LDSS + n * LDSS + seg * 4], Wg + (size_t)n * K + seg * 4);
        }
        cp_commit();
    };

    int S = K / BKx;
    load_stage(0, 0);
    for (int s = 0; s < S; s++) {
        int buf = s & 1;
        if (s + 1 < S) {
            load_stage(s + 1, buf ^ 1);
            asm volatile("cp.async.wait_group 1;" ::: "memory");
        } else {
            asm volatile("cp.async.wait_group 0;" ::: "memory");
        }
        __syncthreads();
        const float* Ab = &As[buf * BM * LDSS];
        const float* Bb = &Bs[buf * BN * LDSS];
        #pragma unroll
        for (int kc = 0; kc < 4; kc++) {
            uint32_t af[4][4];
            #pragma unroll
            for (int mt = 0; mt < 4; mt++) {
                int r = wm + mt * 16 + (lane >> 2);
                const float* p = Ab + r * LDSS + kc * 8 + (lane & 3);
                af[mt][0] = f2tf(p[0]);
                af[mt][1] = f2tf(p[8 * LDSS]);
                af[mt][2] = f2tf(p[4]);
                af[mt][3] = f2tf(p[8 * LDSS + 4]);
            }
            #pragma unroll
            for (int nt = 0; nt < 8; nt++) {
                int n = wn + nt * 8 + (lane >> 2);
                const float* p = Bb + n * LDSS + kc * 8 + (lane & 3);
                uint32_t bf[2] = { f2tf(p[0]), f2tf(p[4]) };
                #pragma unroll
                for (int mt = 0; mt < 4; mt++) mma_tf32(acc[mt][nt], af[mt], bf);
            }
        }
        __syncthreads();
    }

    #pragma unroll
    for (int nt = 0; nt < 8; nt++) {
        int col = n0 + wn + nt * 8 + 2 * (lane & 3);
        float bv0 = bias0[col], bv1 = bias0[col + 1];
        if (bias1) { bv0 += bias1[col]; bv1 += bias1[col + 1]; }
        #pragma unroll
        for (int mt = 0; mt < 4; mt++) {
            int row = m0 + wm + mt * 16 + (lane >> 2);
            float2 v;
            v.x = acc[mt][nt][0] + bv0; v.y = acc[mt][nt][1] + bv1;
            *reinterpret_cast<float2*>(C + (size_t)row * N + col) = v;
            v.x = acc[mt][nt][2] + bv0; v.y = acc[mt][nt][3] + bv1;
            *reinterpret_cast<float2*>(C + (size_t)(row + 8) * N + col) = v;
        }
    }
}

// ---------------- fused per-step kernel ----------------
// Launch s in [0..128]. Blocks 0..63: layer0(step s) GEMM-partials (active if s<128).
// Blocks 64..191: layer1(step s-1) GEMM-partials (active if s>=1).
// Layer0: C[32,4096] = h0_prev[32,1024] @ W_hh0^T   (16 n-tiles x 4 k-slices)
// Layer1: C[32,4096] = hcat_prev[32,2048] @ W1cat^T (16 n-tiles x 8 k-slices)
// Each n-tile = 64 hidden cols x 4 gate strips. Last block per tile (counter)
// reduces partials in FIXED order (deterministic), adds base, does LSTM pointwise.
__global__ void __launch_bounds__(256, 2) step_kernel(const float* __restrict__ Whh0, int s)
{
    int bid = blockIdx.x;
    int layer = (bid >= 64) ? 1 : 0;
    if (!layer && s >= Bdim) return;
    if (layer && s < 1) return;
    int lb = layer ? bid - 64 : bid;
    int jt = lb & 15;
    int ks = lb >> 4;                     // 0..3 (L0) or 0..7 (L1)
    int KS = layer ? 8 : 4;
    int par = s & 1;

    const float* A = g_hcat[par];                       // [32][2048]
    const float* W = layer ? g_W1cat : Whh0;
    int wstride = layer ? 2048 : 1024;
    float* gpart = layer ? g_part1 : g_part0;
    int kbase = ks * 256;

    extern __shared__ float sm[];
    float* As = sm;                 // [2][32][36]
    float* Ws = sm + 2 * 32 * LDSS; // [2][256][36]

    int tid = threadIdx.x, lane = tid & 31, warp = tid >> 5;

    float acc[4][2][4];
    #pragma unroll
    for (int g = 0; g < 4; g++)
        #pragma unroll
        for (int m = 0; m < 2; m++)
            #pragma unroll
            for (int c = 0; c < 4; c++) acc[g][m][c] = 0.f;

    auto load = [&](int cc, int buf) {
        int kw = kbase + cc * 32;
        {
            int row = tid >> 3, seg = tid & 7;
            cp16(&As[(buf * 32 + row) * LDSS + seg * 4], A + row * 2048 + kw + seg * 4);
        }
        #pragma unroll
        for (int i = 0; i < 8; i++) {
            int idx = tid + i * 256;
            int wr = idx >> 3, seg = idx & 7;
            int grow = (wr >> 6) * 1024 + jt * 64 + (wr & 63);
            cp16(&Ws[(buf * 256 + wr) * LDSS + seg * 4], W + (size_t)grow * wstride + kw + seg * 4);
        }
        cp_commit();
    };

    load(0, 0);
    for (int cc = 0; cc < 8; cc++) {
        int buf = cc & 1;
        if (cc < 7) {
            load(cc + 1, buf ^ 1);
            asm volatile("cp.async.wait_group 1;" ::: "memory");
        } else {
            asm volatile("cp.async.wait_group 0;" ::: "memory");
        }
        __syncthreads();
        const float* Ab = As + buf * 32 * LDSS;
        const float* Wb = Ws + buf * 256 * LDSS;
        int r = lane >> 2;
        #pragma unroll
        for (int kc = 0; kc < 4; kc++) {
            int c0 = kc * 8 + (lane & 3);
            uint32_t af[2][4];
            #pragma unroll
            for (int m = 0; m < 2; m++) {
                af[m][0] = f2tf(Ab[(m * 16 + r) * LDSS + c0]);
                af[m][1] = f2tf(Ab[(m * 16 + r + 8) * LDSS + c0]);
                af[m][2] = f2tf(Ab[(m * 16 + r) * LDSS + c0 + 4]);
                af[m][3] = f2tf(Ab[(m * 16 + r + 8) * LDSS + c0 + 4]);
            }
            #pragma unroll
            for (int g = 0; g < 4; g++) {
                int srow = g * 64 + warp * 8 + r;
                uint32_t bf[2] = { f2tf(Wb[srow * LDSS + c0]), f2tf(Wb[srow * LDSS + c0 + 4]) };
                mma_tf32(acc[g][0], af[0], bf);
                mma_tf32(acc[g][1], af[1], bf);
            }
        }
        __syncthreads();
    }

    // store partials (plain STG, fixed slots -> deterministic reduction later)
    #pragma unroll
    for (int g = 0; g < 4; g++) {
        int col = g * 1024 + jt * 64 + warp * 8 + 2 * (lane & 3);
        #pragma unroll
        for (int m = 0; m < 2; m++) {
            int row = m * 16 + (lane >> 2);
            *reinterpret_cast<float2*>(gpart + ((size_t)(ks * 32 + row) * G4 + col)) =
                make_float2(acc[g][m][0], acc[g][m][1]);
            *reinterpret_cast<float2*>(gpart + ((size_t)(ks * 32 + row + 8) * G4 + col)) =
                make_float2(acc[g][m][2], acc[g][m][3]);
        }
    }
    __threadfence();
    __syncthreads();
    __shared__ int lastFlag;
    if (tid == 0) {
        int* cnt = layer ? g_cnt1 : g_cnt0;
        int old = atomicAdd(&cnt[jt], 1);
        lastFlag = (old == KS - 1) ? 1 : 0;
        if (lastFlag) atomicExch(&cnt[jt], 0);   // reset for next launch
    }
    __syncthreads();
    if (!lastFlag) return;
    __threadfence();   // acquire: make other blocks' partials visible

    // ---- epilogue: fixed-order reduce + base + LSTM pointwise ----
    float* hout = g_hcat[par ^ 1];
    #pragma unroll
    for (int i = 0; i < 8; i++) {
        int idx = tid + i * 256;
        int t = idx >> 6, jl = idx & 63;
        int j = jt * 64 + jl;
        float sg[4];
        #pragma unroll
        for (int g = 0; g < 4; g++) {
            float ssum = 0.f;
            for (int k = 0; k < KS; k++)
                ssum += __ldcg(gpart + ((size_t)(k * 32 + t) * G4 + g * 1024 + j));
            sg[g] = ssum;
        }
        if (!layer) {
            #pragma unroll
            for (int g = 0; g < 4; g++)
                sg[g] += g_G0[((size_t)s * 32 + t) * G4 + g * 1024 + j];
            float cn = sigm(sg[1]) * g_c0[t * Hdim + j] + sigm(sg[0]) * tanhf(sg[2]);
            float hn = sigm(sg[3]) * tanhf(cn);
            g_c0[t * Hdim + j] = cn;
            hout[t * 2048 + j] = hn;
        } else {
            #pragma unroll
            for (int g = 0; g < 4; g++)
                sg[g] += g_bias1[g * 1024 + j];
            float cn = sigm(sg[1]) * g_c1[t * Hdim + j] + sigm(sg[0]) * tanhf(sg[2]);
            float hn = sigm(sg[3]) * tanhf(cn);
            g_c1[t * Hdim + j] = cn;
            hout[t * 2048 + 1024 + j] = hn;
            g_ys[((size_t)(s - 1) * 32 + t) * Hdim + j] = hn;
        }
    }
}

// ---------------- launch ----------------
extern "C" void kernel_launch(void* const* d_in, const int* in_sizes, int n_in,
                              void* d_out, int out_size)
{
    const float* features = (const float*)d_in[0];
    const int*   captions = (const int*)d_in[1];
    const float* embed_W  = (const float*)d_in[2];
    const float* W_ih0    = (const float*)d_in[3];
    const float* W_hh0    = (const float*)d_in[4];
    const float* b_ih0    = (const float*)d_in[5];
    const float* b_hh0    = (const float*)d_in[6];
    const float* W_ih1    = (const float*)d_in[7];
    const float* W_hh1    = (const float*)d_in[8];
    const float* b_ih1    = (const float*)d_in[9];
    const float* b_hh1    = (const float*)d_in[10];
    const float* fc_W     = (const float*)d_in[11];
    const float* fc_b     = (const float*)d_in[12];
    float* out = (float*)d_out;

    void *pX = nullptr, *pG0 = nullptr, *pys = nullptr;
    cudaGetSymbolAddress(&pX, g_X);
    cudaGetSymbolAddress(&pG0, g_G0);
    cudaGetSymbolAddress(&pys, g_ys);

    size_t smem_gemm = (size_t)(2 * (BM + BN) * LDSS) * sizeof(float);    // ~108 KB
    cudaFuncSetAttribute(gemm_tf32, cudaFuncAttributeMaxDynamicSharedMemorySize, (int)smem_gemm);
    size_t smem_step = (size_t)(2 * (32 + 256) * LDSS) * sizeof(float);   // ~83 KB
    cudaFuncSetAttribute(step_kernel, cudaFuncAttributeMaxDynamicSharedMemorySize, (int)smem_step);

    init_kernel<<<(Tdim * 2048 + 255) / 256, 256>>>(b_ih1, b_hh1);
    make_w1cat<<<(G4 * 2048 / 4) / 256, 256>>>(W_ih1, W_hh1);
    build_x<<<dim3(Bdim, Tdim), 128>>>(features, captions, embed_W);

    // G0 = X @ W_ih0^T + b_ih0 + b_hh0   (M=4096, N=4096, K=512)
    gemm_tf32<<<dim3(G4 / BM, G4 / BN), 256, smem_gemm>>>(
        (const float*)pX, W_ih0, b_ih0, b_hh0, (float*)pG0, Bdim * Tdim, G4, Edim);

    // fused recurrence: 129 launches
    for (int s = 0; s <= Bdim; s++)
        step_kernel<<<192, 256, smem_step>>>(W_hh0, s);

    // logits = ys @ fc_W^T + fc_b   (M=4096, N=32000, K=1024)
    gemm_tf32<<<dim3((Bdim * Tdim) / BM, Vdim / BN), 256, smem_gemm>>>(
        (const float*)pys, fc_W, fc_b, nullptr, out, Bdim * Tdim, Vdim, Hdim);
}

// round 4
// speedup vs baseline: 1.4319x; 1.4319x over previous
#include <cuda_runtime.h>
#include <cstdint>
#include <math.h>

#define Bdim 128
#define Tdim 32
#define Edim 512
#define Hdim 1024
#define G4   4096
#define Vdim 32000
#define GRID 96

// ---------------- device scratch ----------------
__device__ __align__(16) float g_X[Bdim * Tdim * Edim];        // 8 MB
__device__ __align__(16) float g_G0[Bdim * Tdim * G4];         // 64 MB
__device__ __align__(16) float g_ys[Bdim * Tdim * Hdim];       // 16 MB
__device__ __align__(16) float g_bias1[G4];
__device__ __align__(16) float g_hcat[2][Tdim * 2048];         // [par][t][h0|h1] (tf32-rounded)
__device__ __align__(16) float g_c0[Tdim * Hdim];
__device__ __align__(16) float g_c1[Tdim * Hdim];
__device__ __align__(16) float g_W0[(size_t)G4 * 1024];        // tf32(W_hh0) 16MB
__device__ __align__(16) float g_W1[(size_t)G4 * 2048];        // tf32([Wih1|Whh1]) 32MB
__device__ __align__(16) float g_part0[2 * Tdim * G4];         // 1MB
__device__ __align__(16) float g_part1[4 * Tdim * G4];         // 2MB
__device__ unsigned g_bar;
__device__ unsigned g_phase;

// ---------------- helpers ----------------
__device__ __forceinline__ uint32_t f2tf(float x) {
    uint32_t r;
    asm("cvt.rna.tf32.f32 %0, %1;" : "=r"(r) : "f"(x));
    return r;
}
__device__ __forceinline__ float tf32v(float x) { return __uint_as_float(f2tf(x)); }

__device__ __forceinline__ void mma_tf32(float c[4], const uint32_t a[4], const uint32_t b[2]) {
    asm volatile(
        "mma.sync.aligned.m16n8k8.row.col.f32.tf32.tf32.f32 "
        "{%0,%1,%2,%3}, {%4,%5,%6,%7}, {%8,%9}, {%0,%1,%2,%3};"
        : "+f"(c[0]), "+f"(c[1]), "+f"(c[2]), "+f"(c[3])
        : "r"(a[0]), "r"(a[1]), "r"(a[2]), "r"(a[3]), "r"(b[0]), "r"(b[1]));
}

__device__ __forceinline__ void cp16(float* s, const float* g) {
    uint32_t sa = (uint32_t)__cvta_generic_to_shared(s);
    asm volatile("cp.async.cg.shared.global [%0], [%1], 16;" :: "r"(sa), "l"(g));
}
__device__ __forceinline__ void cp_commit() { asm volatile("cp.async.commit_group;" ::: "memory"); }

__device__ __forceinline__ float sigm(float x) { return 1.f / (1.f + expf(-x)); }

__device__ __forceinline__ unsigned ldcg_u32(const unsigned* p) {
    unsigned v;
    asm volatile("ld.global.cg.u32 %0, [%1];" : "=r"(v) : "l"(p));
    return v;
}

// grid barrier: all GRID blocks arrive, phase counter released by last
__device__ __forceinline__ void grid_bar(unsigned* local_phase) {
    __syncthreads();
    unsigned target = ++(*local_phase);
    if (threadIdx.x == 0) {
        __threadfence();
        unsigned old = atomicAdd(&g_bar, 1);
        if (old == GRID - 1) {
            atomicExch(&g_bar, 0);
            atomicAdd(&g_phase, 1);
        } else {
            while (ldcg_u32(&g_phase) < target) { __nanosleep(40); }
        }
        __threadfence();
    }
    __syncthreads();
}

// ---------------- init ----------------
__global__ void init_kernel(const float* __restrict__ b_ih1, const float* __restrict__ b_hh1) {
    int i = blockIdx.x * blockDim.x + threadIdx.x;
    if (i < Tdim * 2048) { g_hcat[0][i] = 0.f; g_hcat[1][i] = 0.f; }
    if (i < Tdim * Hdim) { g_c0[i] = 0.f; g_c1[i] = 0.f; }
    if (i < G4) g_bias1[i] = b_ih1[i] + b_hh1[i];
    if (i == 0) { g_bar = 0; g_phase = 0; }
}

// pre-round W_hh0 -> g_W0 (tf32 values)
__global__ void round_w0(const float* __restrict__ W) {
    size_t i = (size_t)blockIdx.x * 256 + threadIdx.x;   // float4 index; 1M total
    float4 v = reinterpret_cast<const float4*>(W)[i];
    v.x = tf32v(v.x); v.y = tf32v(v.y); v.z = tf32v(v.z); v.w = tf32v(v.w);
    reinterpret_cast<float4*>(g_W0)[i] = v;
}

// g_W1 = tf32([W_ih1 | W_hh1]) : [4096][2048]
__global__ void make_w1cat(const float* __restrict__ Wi1, const float* __restrict__ Wh1) {
    size_t i = (size_t)blockIdx.x * 256 + threadIdx.x;   // float4 index; 2M total
    int n = (int)(i >> 9);
    int c4 = (int)(i & 511);
    const float4* src = (c4 < 256)
        ? reinterpret_cast<const float4*>(Wi1 + (size_t)n * Hdim) + c4
        : reinterpret_cast<const float4*>(Wh1 + (size_t)n * Hdim) + (c4 - 256);
    float4 v = *src;
    v.x = tf32v(v.x); v.y = tf32v(v.y); v.z = tf32v(v.z); v.w = tf32v(v.w);
    reinterpret_cast<float4*>(g_W1)[i] = v;
}

// ---------------- build X ----------------
__global__ void build_x(const float* __restrict__ features, const int* __restrict__ captions,
                        const float* __restrict__ embW) {
    int b = blockIdx.x, t = blockIdx.y;
    const float* src = (t == 0) ? (features + (size_t)b * Edim)
                                : (embW + (size_t)captions[b * Tdim + t] * Edim);
    float4* dst = reinterpret_cast<float4*>(g_X + ((size_t)b * Tdim + t) * Edim);
    const float4* s4 = reinterpret_cast<const float4*>(src);
    dst[threadIdx.x] = s4[threadIdx.x];
}

// ---------------- big tf32 GEMM (G0 + FC) ----------------
#define BM 128
#define BN 256
#define BKx 32
#define LDSS 36

__global__ void __launch_bounds__(256, 1) gemm_tf32(
    const float* __restrict__ A, const float* __restrict__ W,
    const float* __restrict__ bias0, const float* __restrict__ bias1,
    float* __restrict__ C, int M, int N, int K)
{
    extern __shared__ float smem_f[];
    float* As = smem_f;
    float* Bs = smem_f + 2 * BM * LDSS;

    int tid = threadIdx.x;
    int lane = tid & 31, warp = tid >> 5;
    int m0 = blockIdx.x * BM, n0 = blockIdx.y * BN;
    int wm = (warp >> 2) * 64, wn = (warp & 3) * 64;

    float acc[4][8][4];
    #pragma unroll
    for (int a = 0; a < 4; a++)
        #pragma unroll
        for (int b = 0; b < 8; b++)
            #pragma unroll
            for (int c = 0; c < 4; c++) acc[a][b][c] = 0.f;

    auto load_stage = [&](int s, int buf) {
        int k0 = s * BKx;
        const float* Ag = A + (size_t)m0 * K + k0;
        #pragma unroll
        for (int i = 0; i < 4; i++) {
            int idx = tid + i * 256;
            int m = idx >> 3, seg = idx & 7;
            cp16(&As[buf * BM * LDSS + m * LDSS + seg * 4], Ag + (size_t)m * K + seg * 4);
        }
        const float* Wg = W + (size_t)n0 * K + k0;
        #pragma unroll
        for (int i = 0; i < 8; i++) {
            int idx = tid + i * 256;
            int n = idx >> 3, seg = idx & 7;
            cp16(&Bs[buf * BN * LDSS + n * LDSS + seg * 4], Wg + (size_t)n * K + seg * 4);
        }
        cp_commit();
    };

    int S = K / BKx;
    load_stage(0, 0);
    for (int s = 0; s < S; s++) {
        int buf = s & 1;
        if (s + 1 < S) {
            load_stage(s + 1, buf ^ 1);
            asm volatile("cp.async.wait_group 1;" ::: "memory");
        } else {
            asm volatile("cp.async.wait_group 0;" ::: "memory");
        }
        __syncthreads();
        const float* Ab = &As[buf * BM * LDSS];
        const float* Bb = &Bs[buf * BN * LDSS];
        #pragma unroll
        for (int kc = 0; kc < 4; kc++) {
            uint32_t af[4][4];
            #pragma unroll
            for (int mt = 0; mt < 4; mt++) {
                int r = wm + mt * 16 + (lane >> 2);
                const float* p = Ab + r * LDSS + kc * 8 + (lane & 3);
                af[mt][0] = f2tf(p[0]);
                af[mt][1] = f2tf(p[8 * LDSS]);
                af[mt][2] = f2tf(p[4]);
                af[mt][3] = f2tf(p[8 * LDSS + 4]);
            }
            #pragma unroll
            for (int nt = 0; nt < 8; nt++) {
                int n = wn + nt * 8 + (lane >> 2);
                const float* p = Bb + n * LDSS + kc * 8 + (lane & 3);
                uint32_t bf[2] = { f2tf(p[0]), f2tf(p[4]) };
                #pragma unroll
                for (int mt = 0; mt < 4; mt++) mma_tf32(acc[mt][nt], af[mt], bf);
            }
        }
        __syncthreads();
    }

    #pragma unroll
    for (int nt = 0; nt < 8; nt++) {
        int col = n0 + wn + nt * 8 + 2 * (lane & 3);
        float bv0 = bias0[col], bv1 = bias0[col + 1];
        if (bias1) { bv0 += bias1[col]; bv1 += bias1[col + 1]; }
        #pragma unroll
        for (int mt = 0; mt < 4; mt++) {
            int row = m0 + wm + mt * 16 + (lane >> 2);
            float2 v;
            v.x = acc[mt][nt][0] + bv0; v.y = acc[mt][nt][1] + bv1;
            *reinterpret_cast<float2*>(C + (size_t)row * N + col) = v;
            v.x = acc[mt][nt][2] + bv0; v.y = acc[mt][nt][3] + bv1;
            *reinterpret_cast<float2*>(C + (size_t)(row + 8) * N + col) = v;
        }
    }
}

// ---------------- persistent recurrence kernel ----------------
// 96 blocks, 1/SM, all co-resident. 129 steps, 2 grid barriers per step.
// Blocks 0..31  : layer0  jt = b>>1 (64 cols x 4 gates), ks = b&1 (K=512)
// Blocks 32..95 : layer1  jt = lb>>2, ks = lb&3 (K=512)
// All operands pre-rounded to tf32 -> no cvt in mainloop.
__global__ void __launch_bounds__(256, 1) recurrence_kernel()
{
    extern __shared__ float sm[];
    float* As = sm;                 // [2][32][36]
    float* Ws = sm + 2 * 32 * LDSS; // [2][256][36]

    int bid = blockIdx.x;
    int tid = threadIdx.x, lane = tid & 31, warp = tid >> 5;
    int layer = (bid >= 32) ? 1 : 0;
    int jt, ks;
    if (!layer) { jt = bid >> 1; ks = bid & 1; }
    else        { int lb = bid - 32; jt = lb >> 2; ks = lb & 3; }
    int kbase = ks * 512;
    const float* W = layer ? g_W1 : g_W0;
    int wstride = layer ? 2048 : 1024;
    float* gpart = layer ? g_part1 : g_part0;

    unsigned local_phase = 0;

    for (int s = 0; s <= Bdim; s++) {
        int par = s & 1;

        bool active = layer ? (s >= 1) : (s < Bdim);

        if (active) {
            const float* A = g_hcat[par];

            float acc[4][2][4];
            #pragma unroll
            for (int g = 0; g < 4; g++)
                #pragma unroll
                for (int m = 0; m < 2; m++)
                    #pragma unroll
                    for (int c = 0; c < 4; c++) acc[g][m][c] = 0.f;

            auto load = [&](int cc, int buf) {
                int kw = kbase + cc * 32;
                {
                    int row = tid >> 3, seg = tid & 7;
                    cp16(&As[(buf * 32 + row) * LDSS + seg * 4], A + row * 2048 + kw + seg * 4);
                }
                #pragma unroll
                for (int i = 0; i < 8; i++) {
                    int idx = tid + i * 256;
                    int wr = idx >> 3, seg = idx & 7;
                    int grow = (wr >> 6) * 1024 + jt * 64 + (wr & 63);
                    cp16(&Ws[(buf * 256 + wr) * LDSS + seg * 4],
                         W + (size_t)grow * wstride + kw + seg * 4);
                }
                cp_commit();
            };

            load(0, 0);
            for (int cc = 0; cc < 16; cc++) {
                int buf = cc & 1;
                if (cc < 15) {
                    load(cc + 1, buf ^ 1);
                    asm volatile("cp.async.wait_group 1;" ::: "memory");
                } else {
                    asm volatile("cp.async.wait_group 0;" ::: "memory");
                }
                __syncthreads();
                const float* Ab = As + buf * 32 * LDSS;
                const float* Wb = Ws + buf * 256 * LDSS;
                int r = lane >> 2;
                #pragma unroll
                for (int kc = 0; kc < 4; kc++) {
                    int c0 = kc * 8 + (lane & 3);
                    uint32_t af[2][4];
                    #pragma unroll
                    for (int m = 0; m < 2; m++) {
                        af[m][0] = __float_as_uint(Ab[(m * 16 + r) * LDSS + c0]);
                        af[m][1] = __float_as_uint(Ab[(m * 16 + r + 8) * LDSS + c0]);
                        af[m][2] = __float_as_uint(Ab[(m * 16 + r) * LDSS + c0 + 4]);
                        af[m][3] = __float_as_uint(Ab[(m * 16 + r + 8) * LDSS + c0 + 4]);
                    }
                    #pragma unroll
                    for (int g = 0; g < 4; g++) {
                        int srow = g * 64 + warp * 8 + r;
                        uint32_t bf[2] = { __float_as_uint(Wb[srow * LDSS + c0]),
                                           __float_as_uint(Wb[srow * LDSS + c0 + 4]) };
                        mma_tf32(acc[g][0], af[0], bf);
                        mma_tf32(acc[g][1], af[1], bf);
                    }
                }
                __syncthreads();
            }

            // store partials to fixed slots
            #pragma unroll
            for (int g = 0; g < 4; g++) {
                int col = g * 1024 + jt * 64 + warp * 8 + 2 * (lane & 3);
                #pragma unroll
                for (int m = 0; m < 2; m++) {
                    int row = m * 16 + (lane >> 2);
                    *reinterpret_cast<float2*>(gpart + ((size_t)(ks * 32 + row) * G4 + col)) =
                        make_float2(acc[g][m][0], acc[g][m][1]);
                    *reinterpret_cast<float2*>(gpart + ((size_t)(ks * 32 + row + 8) * G4 + col)) =
                        make_float2(acc[g][m][2], acc[g][m][3]);
                }
            }
        }

        grid_bar(&local_phase);

        // ---- distributed epilogue (fixed-order reduce, deterministic) ----
        float* hout = g_hcat[par ^ 1];
        if (!layer) {
            if (s < Bdim) {
                int th = (bid & 1) * 16;   // 16 t-rows
                #pragma unroll
                for (int i = 0; i < 4; i++) {
                    int idx = tid + i * 256;
                    int t = th + (idx >> 6), j = jt * 64 + (idx & 63);
                    float sg[4];
                    #pragma unroll
                    for (int g = 0; g < 4; g++) {
                        sg[g] = __ldcg(g_part0 + ((size_t)(0 * 32 + t) * G4 + g * 1024 + j))
                              + __ldcg(g_part0 + ((size_t)(1 * 32 + t) * G4 + g * 1024 + j))
                              + g_G0[((size_t)s * 32 + t) * G4 + g * 1024 + j];
                    }
                    float cn = sigm(sg[1]) * g_c0[t * Hdim + j] + sigm(sg[0]) * tanhf(sg[2]);
                    float hn = sigm(sg[3]) * tanhf(cn);
                    g_c0[t * Hdim + j] = cn;
                    hout[t * 2048 + j] = tf32v(hn);
                }
            }
        } else {
            if (s >= 1) {
                int lb = bid - 32;
                int tq = (lb & 3) * 8;     // 8 t-rows
                #pragma unroll
                for (int i = 0; i < 2; i++) {
                    int idx = tid + i * 256;
                    int t = tq + (idx >> 6), j = jt * 64 + (idx & 63);
                    float sg[4];
                    #pragma unroll
                    for (int g = 0; g < 4; g++) {
                        float ssum = g_bias1[g * 1024 + j];
                        #pragma unroll
                        for (int k = 0; k < 4; k++)
                            ssum += __ldcg(g_part1 + ((size_t)(k * 32 + t) * G4 + g * 1024 + j));
                        sg[g] = ssum;
                    }
                    float cn = sigm(sg[1]) * g_c1[t * Hdim + j] + sigm(sg[0]) * tanhf(sg[2]);
                    float hn = sigm(sg[3]) * tanhf(cn);
                    g_c1[t * Hdim + j] = cn;
                    float hr = tf32v(hn);
                    hout[t * 2048 + 1024 + j] = hr;
                    g_ys[((size_t)(s - 1) * 32 + t) * Hdim + j] = hr;
                }
            }
        }

        grid_bar(&local_phase);
    }
}

// ---------------- launch ----------------
extern "C" void kernel_launch(void* const* d_in, const int* in_sizes, int n_in,
                              void* d_out, int out_size)
{
    const float* features = (const float*)d_in[0];
    const int*   captions = (const int*)d_in[1];
    const float* embed_W  = (const float*)d_in[2];
    const float* W_ih0    = (const float*)d_in[3];
    const float* W_hh0    = (const float*)d_in[4];
    const float* b_ih0    = (const float*)d_in[5];
    const float* b_hh0    = (const float*)d_in[6];
    const float* W_ih1    = (const float*)d_in[7];
    const float* W_hh1    = (const float*)d_in[8];
    const float* b_ih1    = (const float*)d_in[9];
    const float* b_hh1    = (const float*)d_in[10];
    const float* fc_W     = (const float*)d_in[11];
    const float* fc_b     = (const float*)d_in[12];
    float* out = (float*)d_out;

    void *pX = nullptr, *pG0 = nullptr, *pys = nullptr;
    cudaGetSymbolAddress(&pX, g_X);
    cudaGetSymbolAddress(&pG0, g_G0);
    cudaGetSymbolAddress(&pys, g_ys);

    size_t smem_gemm = (size_t)(2 * (BM + BN) * LDSS) * sizeof(float);    // ~108 KB
    cudaFuncSetAttribute(gemm_tf32, cudaFuncAttributeMaxDynamicSharedMemorySize, (int)smem_gemm);
    size_t smem_step = (size_t)(2 * (32 + 256) * LDSS) * sizeof(float);   // ~83 KB
    cudaFuncSetAttribute(recurrence_kernel, cudaFuncAttributeMaxDynamicSharedMemorySize, (int)smem_step);

    init_kernel<<<(Tdim * 2048 + 255) / 256, 256>>>(b_ih1, b_hh1);
    round_w0<<<(G4 * 1024 / 4) / 256, 256>>>(W_hh0);
    make_w1cat<<<(G4 * 2048 / 4) / 256, 256>>>(W_ih1, W_hh1);
    build_x<<<dim3(Bdim, Tdim), 128>>>(features, captions, embed_W);

    // G0 = X @ W_ih0^T + b_ih0 + b_hh0   (M=4096, N=4096, K=512)
    gemm_tf32<<<dim3(G4 / BM, G4 / BN), 256, smem_gemm>>>(
        (const float*)pX, W_ih0, b_ih0, b_hh0, (float*)pG0, Bdim * Tdim, G4, Edim);

    // persistent recurrence: all 129 fused steps in one launch
    recurrence_kernel<<<GRID, 256, smem_step>>>();

    // logits = ys @ fc_W^T + fc_b   (M=4096, N=32000, K=1024)
    gemm_tf32<<<dim3((Bdim * Tdim) / BM, Vdim / BN), 256, smem_gemm>>>(
        (const float*)pys, fc_W, fc_b, nullptr, out, Bdim * Tdim, Vdim, Hdim);
}

// round 5
// speedup vs baseline: 1.6181x; 1.1300x over previous
#include <cuda_runtime.h>
#include <cstdint>
#include <math.h>

#define Bdim 128
#define Tdim 32
#define Edim 512
#define Hdim 1024
#define G4   4096
#define Vdim 32000
#define GRID 144

// ---------------- device scratch ----------------
__device__ __align__(16) float g_X[Bdim * Tdim * Edim];        // 8 MB
__device__ __align__(16) float g_G0[Bdim * Tdim * G4];         // 64 MB
__device__ __align__(16) float g_ys[Bdim * Tdim * Hdim];       // 16 MB
__device__ __align__(16) float g_bias1[G4];
__device__ __align__(16) float g_hcat[2][Tdim * 2048];         // [par][t][h0|h1] (tf32-rounded)
__device__ __align__(16) float g_c0[Tdim * Hdim];
__device__ __align__(16) float g_c1[Tdim * Hdim];
__device__ __align__(16) float g_W0[(size_t)G4 * 1024];        // tf32(W_hh0) 16MB
__device__ __align__(16) float g_W1[(size_t)G4 * 2048];        // tf32([Wih1|Whh1]) 32MB
__device__ __align__(16) float g_part0[3 * Tdim * G4];         // 1.5MB
__device__ __align__(16) float g_part1[6 * Tdim * G4];         // 3MB
__device__ unsigned g_bar;
__device__ unsigned g_phase;

// ---------------- helpers ----------------
__device__ __forceinline__ uint32_t f2tf(float x) {
    uint32_t r;
    asm("cvt.rna.tf32.f32 %0, %1;" : "=r"(r) : "f"(x));
    return r;
}
__device__ __forceinline__ float tf32v(float x) { return __uint_as_float(f2tf(x)); }

__device__ __forceinline__ void mma_tf32(float c[4], const uint32_t a[4], const uint32_t b[2]) {
    asm volatile(
        "mma.sync.aligned.m16n8k8.row.col.f32.tf32.tf32.f32 "
        "{%0,%1,%2,%3}, {%4,%5,%6,%7}, {%8,%9}, {%0,%1,%2,%3};"
        : "+f"(c[0]), "+f"(c[1]), "+f"(c[2]), "+f"(c[3])
        : "r"(a[0]), "r"(a[1]), "r"(a[2]), "r"(a[3]), "r"(b[0]), "r"(b[1]));
}

__device__ __forceinline__ void cp16(float* s, const float* g) {
    uint32_t sa = (uint32_t)__cvta_generic_to_shared(s);
    asm volatile("cp.async.cg.shared.global [%0], [%1], 16;" :: "r"(sa), "l"(g));
}
__device__ __forceinline__ void cp_commit() { asm volatile("cp.async.commit_group;" ::: "memory"); }

__device__ __forceinline__ float sigm(float x) { return 1.f / (1.f + expf(-x)); }

__device__ __forceinline__ unsigned ldcg_u32(const unsigned* p) {
    unsigned v;
    asm volatile("ld.global.cg.u32 %0, [%1];" : "=r"(v) : "l"(p));
    return v;
}

// grid barrier: all GRID blocks arrive, phase counter released by last
__device__ __forceinline__ void grid_bar(unsigned* local_phase) {
    __syncthreads();
    unsigned target = ++(*local_phase);
    if (threadIdx.x == 0) {
        __threadfence();
        unsigned old = atomicAdd(&g_bar, 1);
        if (old == GRID - 1) {
            atomicExch(&g_bar, 0);
            atomicAdd(&g_phase, 1);
        } else {
            while (ldcg_u32(&g_phase) < target) { __nanosleep(40); }
        }
        __threadfence();
    }
    __syncthreads();
}

// ---------------- init ----------------
__global__ void init_kernel(const float* __restrict__ b_ih1, const float* __restrict__ b_hh1) {
    int i = blockIdx.x * blockDim.x + threadIdx.x;
    if (i < Tdim * 2048) { g_hcat[0][i] = 0.f; g_hcat[1][i] = 0.f; }
    if (i < Tdim * Hdim) { g_c0[i] = 0.f; g_c1[i] = 0.f; }
    if (i < G4) g_bias1[i] = b_ih1[i] + b_hh1[i];
    if (i == 0) { g_bar = 0; g_phase = 0; }
}

// pre-round W_hh0 -> g_W0 (tf32 values)
__global__ void round_w0(const float* __restrict__ W) {
    size_t i = (size_t)blockIdx.x * 256 + threadIdx.x;   // float4 index; 1M total
    float4 v = reinterpret_cast<const float4*>(W)[i];
    v.x = tf32v(v.x); v.y = tf32v(v.y); v.z = tf32v(v.z); v.w = tf32v(v.w);
    reinterpret_cast<float4*>(g_W0)[i] = v;
}

// g_W1 = tf32([W_ih1 | W_hh1]) : [4096][2048]
__global__ void make_w1cat(const float* __restrict__ Wi1, const float* __restrict__ Wh1) {
    size_t i = (size_t)blockIdx.x * 256 + threadIdx.x;   // float4 index; 2M total
    int n = (int)(i >> 9);
    int c4 = (int)(i & 511);
    const float4* src = (c4 < 256)
        ? reinterpret_cast<const float4*>(Wi1 + (size_t)n * Hdim) + c4
        : reinterpret_cast<const float4*>(Wh1 + (size_t)n * Hdim) + (c4 - 256);
    float4 v = *src;
    v.x = tf32v(v.x); v.y = tf32v(v.y); v.z = tf32v(v.z); v.w = tf32v(v.w);
    reinterpret_cast<float4*>(g_W1)[i] = v;
}

// ---------------- build X ----------------
__global__ void build_x(const float* __restrict__ features, const int* __restrict__ captions,
                        const float* __restrict__ embW) {
    int b = blockIdx.x, t = blockIdx.y;
    const float* src = (t == 0) ? (features + (size_t)b * Edim)
                                : (embW + (size_t)captions[b * Tdim + t] * Edim);
    float4* dst = reinterpret_cast<float4*>(g_X + ((size_t)b * Tdim + t) * Edim);
    const float4* s4 = reinterpret_cast<const float4*>(src);
    dst[threadIdx.x] = s4[threadIdx.x];
}

// ---------------- big tf32 GEMM (G0 + FC) ----------------
#define BM 128
#define BN 256
#define BKx 32
#define LDSS 36

__global__ void __launch_bounds__(256, 1) gemm_tf32(
    const float* __restrict__ A, const float* __restrict__ W,
    const float* __restrict__ bias0, const float* __restrict__ bias1,
    float* __restrict__ C, int M, int N, int K)
{
    extern __shared__ float smem_f[];
    float* As = smem_f;
    float* Bs = smem_f + 2 * BM * LDSS;

    int tid = threadIdx.x;
    int lane = tid & 31, warp = tid >> 5;
    int m0 = blockIdx.x * BM, n0 = blockIdx.y * BN;
    int wm = (warp >> 2) * 64, wn = (warp & 3) * 64;

    float acc[4][8][4];
    #pragma unroll
    for (int a = 0; a < 4; a++)
        #pragma unroll
        for (int b = 0; b < 8; b++)
            #pragma unroll
            for (int c = 0; c < 4; c++) acc[a][b][c] = 0.f;

    auto load_stage = [&](int s, int buf) {
        int k0 = s * BKx;
        const float* Ag = A + (size_t)m0 * K + k0;
        #pragma unroll
        for (int i = 0; i < 4; i++) {
            int idx = tid + i * 256;
            int m = idx >> 3, seg = idx & 7;
            cp16(&As[buf * BM * LDSS + m * LDSS + seg * 4], Ag + (size_t)m * K + seg * 4);
        }
        const float* Wg = W + (size_t)n0 * K + k0;
        #pragma unroll
        for (int i = 0; i < 8; i++) {
            int idx = tid + i * 256;
            int n = idx >> 3, seg = idx & 7;
            cp16(&Bs[buf * BN * LDSS + n * LDSS + seg * 4], Wg + (size_t)n * K + seg * 4);
        }
        cp_commit();
    };

    int S = K / BKx;
    load_stage(0, 0);
    for (int s = 0; s < S; s++) {
        int buf = s & 1;
        if (s + 1 < S) {
            load_stage(s + 1, buf ^ 1);
            asm volatile("cp.async.wait_group 1;" ::: "memory");
        } else {
            asm volatile("cp.async.wait_group 0;" ::: "memory");
        }
        __syncthreads();
        const float* Ab = &As[buf * BM * LDSS];
        const float* Bb = &Bs[buf * BN * LDSS];
        #pragma unroll
        for (int kc = 0; kc < 4; kc++) {
            uint32_t af[4][4];
            #pragma unroll
            for (int mt = 0; mt < 4; mt++) {
                int r = wm + mt * 16 + (lane >> 2);
                const float* p = Ab + r * LDSS + kc * 8 + (lane & 3);
                af[mt][0] = f2tf(p[0]);
                af[mt][1] = f2tf(p[8 * LDSS]);
                af[mt][2] = f2tf(p[4]);
                af[mt][3] = f2tf(p[8 * LDSS + 4]);
            }
            #pragma unroll
            for (int nt = 0; nt < 8; nt++) {
                int n = wn + nt * 8 + (lane >> 2);
                const float* p = Bb + n * LDSS + kc * 8 + (lane & 3);
                uint32_t bf[2] = { f2tf(p[0]), f2tf(p[4]) };
                #pragma unroll
                for (int mt = 0; mt < 4; mt++) mma_tf32(acc[mt][nt], af[mt], bf);
            }
        }
        __syncthreads();
    }

    #pragma unroll
    for (int nt = 0; nt < 8; nt++) {
        int col = n0 + wn + nt * 8 + 2 * (lane & 3);
        float bv0 = bias0[col], bv1 = bias0[col + 1];
        if (bias1) { bv0 += bias1[col]; bv1 += bias1[col + 1]; }
        #pragma unroll
        for (int mt = 0; mt < 4; mt++) {
            int row = m0 + wm + mt * 16 + (lane >> 2);
            float2 v;
            v.x = acc[mt][nt][0] + bv0; v.y = acc[mt][nt][1] + bv1;
            *reinterpret_cast<float2*>(C + (size_t)row * N + col) = v;
            v.x = acc[mt][nt][2] + bv0; v.y = acc[mt][nt][3] + bv1;
            *reinterpret_cast<float2*>(C + (size_t)(row + 8) * N + col) = v;
        }
    }
}

// ---------------- persistent recurrence kernel ----------------
// 144 blocks (<=148 SMs, 1/SM), 512 threads = 16 warps (4/SMSP).
// Blocks 0..47  : layer0  jt = b/3  (64 cols x 4 gates), ks = b%3  over K=1024
// Blocks 48..143: layer1  jt = lb/6, ks = lb%6 over K=2048
// Each warp owns 16 W-rows of the 256-row tile (2 n8 subtiles).
// All operands pre-rounded to tf32 -> no cvt in mainloop.
__global__ void __launch_bounds__(512, 1) recurrence_kernel()
{
    extern __shared__ float sm[];
    float* As = sm;                 // [2][32][36]
    float* Ws = sm + 2 * 32 * LDSS; // [2][256][36]

    int bid = blockIdx.x;
    int tid = threadIdx.x, lane = tid & 31, warp = tid >> 5;
    int layer = (bid >= 48) ? 1 : 0;
    int jt, ks, cstart, ccnt, tstart, tcnt;
    if (!layer) {
        jt = bid / 3; ks = bid % 3;
        cstart = ks * 11; ccnt = (ks == 2) ? 10 : 11;          // 32 chunks total
        tstart = ks * 11; tcnt = (ks == 2) ? 10 : 11;          // epilogue t-split
    } else {
        int lb = bid - 48;
        jt = lb / 6; ks = lb % 6;
        cstart = (ks < 4) ? ks * 11 : 44 + (ks - 4) * 10;      // 64 chunks total
        ccnt = (ks < 4) ? 11 : 10;
        tstart = (ks < 4) ? ks * 6 : 24 + (ks - 4) * 4;
        tcnt = (ks < 4) ? 6 : 4;
    }
    const float* W = layer ? g_W1 : g_W0;
    int wstride = layer ? 2048 : 1024;
    float* gpart = layer ? g_part1 : g_part0;

    unsigned local_phase = 0;

    for (int s = 0; s <= Bdim; s++) {
        int par = s & 1;
        bool active = layer ? (s >= 1) : (s < Bdim);

        if (active) {
            const float* A = g_hcat[par];

            float acc[2][2][4];
            #pragma unroll
            for (int nt = 0; nt < 2; nt++)
                #pragma unroll
                for (int m = 0; m < 2; m++)
                    #pragma unroll
                    for (int c = 0; c < 4; c++) acc[nt][m][c] = 0.f;

            auto load = [&](int c, int buf) {
                int kw = c * 32;
                if (tid < 256) {
                    int row = tid >> 3, seg = tid & 7;
                    cp16(&As[(buf * 32 + row) * LDSS + seg * 4], A + row * 2048 + kw + seg * 4);
                }
                #pragma unroll
                for (int i = 0; i < 4; i++) {
                    int idx = tid + i * 512;
                    int wr = idx >> 3, seg = idx & 7;
                    int grow = (wr >> 6) * 1024 + jt * 64 + (wr & 63);
                    cp16(&Ws[(buf * 256 + wr) * LDSS + seg * 4],
                         W + (size_t)grow * wstride + kw + seg * 4);
                }
                cp_commit();
            };

            load(cstart, 0);
            for (int cc = 0; cc < ccnt; cc++) {
                int buf = cc & 1;
                if (cc + 1 < ccnt) {
                    load(cstart + cc + 1, buf ^ 1);
                    asm volatile("cp.async.wait_group 1;" ::: "memory");
                } else {
                    asm volatile("cp.async.wait_group 0;" ::: "memory");
                }
                __syncthreads();
                const float* Ab = As + buf * 32 * LDSS;
                const float* Wb = Ws + buf * 256 * LDSS;
                int r = lane >> 2;
                #pragma unroll
                for (int kc = 0; kc < 4; kc++) {
                    int c0 = kc * 8 + (lane & 3);
                    uint32_t af[2][4];
                    #pragma unroll
                    for (int m = 0; m < 2; m++) {
                        af[m][0] = __float_as_uint(Ab[(m * 16 + r) * LDSS + c0]);
                        af[m][1] = __float_as_uint(Ab[(m * 16 + r + 8) * LDSS + c0]);
                        af[m][2] = __float_as_uint(Ab[(m * 16 + r) * LDSS + c0 + 4]);
                        af[m][3] = __float_as_uint(Ab[(m * 16 + r + 8) * LDSS + c0 + 4]);
                    }
                    #pragma unroll
                    for (int nt = 0; nt < 2; nt++) {
                        int srow = warp * 16 + nt * 8 + r;
                        uint32_t bf[2] = { __float_as_uint(Wb[srow * LDSS + c0]),
                                           __float_as_uint(Wb[srow * LDSS + c0 + 4]) };
                        mma_tf32(acc[nt][0], af[0], bf);
                        mma_tf32(acc[nt][1], af[1], bf);
                    }
                }
                __syncthreads();
            }

            // store partials to fixed slots
            #pragma unroll
            for (int nt = 0; nt < 2; nt++) {
                int col = (warp >> 2) * 1024 + jt * 64 + (warp & 3) * 16 + nt * 8 + 2 * (lane & 3);
                #pragma unroll
                for (int m = 0; m < 2; m++) {
                    int row = m * 16 + (lane >> 2);
                    *reinterpret_cast<float2*>(gpart + ((size_t)(ks * 32 + row) * G4 + col)) =
                        make_float2(acc[nt][m][0], acc[nt][m][1]);
                    *reinterpret_cast<float2*>(gpart + ((size_t)(ks * 32 + row + 8) * G4 + col)) =
                        make_float2(acc[nt][m][2], acc[nt][m][3]);
                }
            }
        }

        grid_bar(&local_phase);

        // ---- distributed epilogue (fixed-order reduce, deterministic) ----
        float* hout = g_hcat[par ^ 1];
        if (!layer) {
            if (s < Bdim) {
                int elems = tcnt * 64;
                #pragma unroll
                for (int i = 0; i < 2; i++) {
                    int idx = tid + i * 512;
                    if (idx < elems) {
                        int t = tstart + (idx >> 6), j = jt * 64 + (idx & 63);
                        float sg[4];
                        #pragma unroll
                        for (int g = 0; g < 4; g++) {
                            sg[g] = __ldcg(g_part0 + ((size_t)(0 * 32 + t) * G4 + g * 1024 + j))
                                  + __ldcg(g_part0 + ((size_t)(1 * 32 + t) * G4 + g * 1024 + j))
                                  + __ldcg(g_part0 + ((size_t)(2 * 32 + t) * G4 + g * 1024 + j))
                                  + g_G0[((size_t)s * 32 + t) * G4 + g * 1024 + j];
                        }
                        float cn = sigm(sg[1]) * g_c0[t * Hdim + j] + sigm(sg[0]) * tanhf(sg[2]);
                        float hn = sigm(sg[3]) * tanhf(cn);
                        g_c0[t * Hdim + j] = cn;
                        hout[t * 2048 + j] = tf32v(hn);
                    }
                }
            }
        } else {
            if (s >= 1) {
                int elems = tcnt * 64;
                int idx = tid;
                if (idx < elems) {
                    int t = tstart + (idx >> 6), j = jt * 64 + (idx & 63);
                    float sg[4];
                    #pragma unroll
                    for (int g = 0; g < 4; g++) {
                        float ssum = g_bias1[g * 1024 + j];
                        #pragma unroll
                        for (int k = 0; k < 6; k++)
                            ssum += __ldcg(g_part1 + ((size_t)(k * 32 + t) * G4 + g * 1024 + j));
                        sg[g] = ssum;
                    }
                    float cn = sigm(sg[1]) * g_c1[t * Hdim + j] + sigm(sg[0]) * tanhf(sg[2]);
                    float hn = sigm(sg[3]) * tanhf(cn);
                    g_c1[t * Hdim + j] = cn;
                    float hr = tf32v(hn);
                    hout[t * 2048 + 1024 + j] = hr;
                    g_ys[((size_t)(s - 1) * 32 + t) * Hdim + j] = hr;
                }
            }
        }

        grid_bar(&local_phase);
    }
}

// ---------------- launch ----------------
extern "C" void kernel_launch(void* const* d_in, const int* in_sizes, int n_in,
                              void* d_out, int out_size)
{
    const float* features = (const float*)d_in[0];
    const int*   captions = (const int*)d_in[1];
    const float* embed_W  = (const float*)d_in[2];
    const float* W_ih0    = (const float*)d_in[3];
    const float* W_hh0    = (const float*)d_in[4];
    const float* b_ih0    = (const float*)d_in[5];
    const float* b_hh0    = (const float*)d_in[6];
    const float* W_ih1    = (const float*)d_in[7];
    const float* W_hh1    = (const float*)d_in[8];
    const float* b_ih1    = (const float*)d_in[9];
    const float* b_hh1    = (const float*)d_in[10];
    const float* fc_W     = (const float*)d_in[11];
    const float* fc_b     = (const float*)d_in[12];
    float* out = (float*)d_out;

    void *pX = nullptr, *pG0 = nullptr, *pys = nullptr;
    cudaGetSymbolAddress(&pX, g_X);
    cudaGetSymbolAddress(&pG0, g_G0);
    cudaGetSymbolAddress(&pys, g_ys);

    size_t smem_gemm = (size_t)(2 * (BM + BN) * LDSS) * sizeof(float);    // ~108 KB
    cudaFuncSetAttribute(gemm_tf32, cudaFuncAttributeMaxDynamicSharedMemorySize, (int)smem_gemm);
    size_t smem_step = (size_t)(2 * (32 + 256) * LDSS) * sizeof(float);   // ~83 KB
    cudaFuncSetAttribute(recurrence_kernel, cudaFuncAttributeMaxDynamicSharedMemorySize, (int)smem_step);

    init_kernel<<<(Tdim * 2048 + 255) / 256, 256>>>(b_ih1, b_hh1);
    round_w0<<<(G4 * 1024 / 4) / 256, 256>>>(W_hh0);
    make_w1cat<<<(G4 * 2048 / 4) / 256, 256>>>(W_ih1, W_hh1);
    build_x<<<dim3(Bdim, Tdim), 128>>>(features, captions, embed_W);

    // G0 = X @ W_ih0^T + b_ih0 + b_hh0   (M=4096, N=4096, K=512)
    gemm_tf32<<<dim3(G4 / BM, G4 / BN), 256, smem_gemm>>>(
        (const float*)pX, W_ih0, b_ih0, b_hh0, (float*)pG0, Bdim * Tdim, G4, Edim);

    // persistent recurrence: all 129 fused steps in one launch
    recurrence_kernel<<<GRID, 512, smem_step>>>();

    // logits = ys @ fc_W^T + fc_b   (M=4096, N=32000, K=1024)
    gemm_tf32<<<dim3((Bdim * Tdim) / BM, Vdim / BN), 256, smem_gemm>>>(
        (const float*)pys, fc_W, fc_b, nullptr, out, Bdim * Tdim, Vdim, Hdim);
}

// round 8
// speedup vs baseline: 2.5778x; 1.5931x over previous
#include <cuda_runtime.h>
#include <cuda_fp16.h>
#include <cstdint>
#include <math.h>

#define Bdim 128
#define Tdim 32
#define Edim 512
#define Hdim 1024
#define G4   4096
#define Vdim 32000
#define GRID 144
#define LDSS 36   // u32 words per SMEM row (32 data + 4 pad) -> conflict-free

// ---------------- device scratch ----------------
__device__ __align__(16) __half g_Xh[Bdim * Tdim * Edim];          // 4 MB
__device__ __align__(16) float  g_G0[Bdim * Tdim * G4];            // 64 MB
__device__ __align__(16) __half g_ysh[Bdim * Tdim * Hdim];         // 8 MB
__device__ __align__(16) float  g_bias1[G4];
__device__ __align__(16) __half g_hcath[2][Tdim * 2048];           // [par][t][h0|h1]
__device__ __align__(16) float  g_c0[Tdim * Hdim];
__device__ __align__(16) float  g_c1[Tdim * Hdim];
__device__ __align__(16) __half g_W0h[(size_t)G4 * 1024];          // fp16(W_hh0) 8MB
__device__ __align__(16) __half g_W1h[(size_t)G4 * 2048];          // fp16([Wih1|Whh1]) 16MB
__device__ __align__(16) __half g_Wih0h[(size_t)G4 * 512];         // fp16(W_ih0) 4MB
__device__ __align__(16) __half g_fcWh[(size_t)Vdim * 1024];       // fp16(fc_W) 64MB
__device__ __align__(16) float  g_part0[3 * Tdim * G4];            // 1.5MB
__device__ __align__(16) float  g_part1[6 * Tdim * G4];            // 3MB
__device__ unsigned g_bar;
__device__ unsigned g_phase;

// ---------------- helpers ----------------
__device__ __forceinline__ uint32_t pack2(float a, float b) {
    __half2 h = __floats2half2_rn(a, b);
    return *reinterpret_cast<uint32_t*>(&h);
}

__device__ __forceinline__ void mma_f16(float c[4], const uint32_t a[4], const uint32_t b[2]) {
    asm volatile(
        "mma.sync.aligned.m16n8k16.row.col.f32.f16.f16.f32 "
        "{%0,%1,%2,%3}, {%4,%5,%6,%7}, {%8,%9}, {%0,%1,%2,%3};"
        : "+f"(c[0]), "+f"(c[1]), "+f"(c[2]), "+f"(c[3])
        : "r"(a[0]), "r"(a[1]), "r"(a[2]), "r"(a[3]), "r"(b[0]), "r"(b[1]));
}

__device__ __forceinline__ void cp16(void* s, const void* g) {
    uint32_t sa = (uint32_t)__cvta_generic_to_shared(s);
    asm volatile("cp.async.cg.shared.global [%0], [%1], 16;" :: "r"(sa), "l"(g));
}
__device__ __forceinline__ void cp_commit() { asm volatile("cp.async.commit_group;" ::: "memory"); }

__device__ __forceinline__ float sigm(float x) { return 1.f / (1.f + expf(-x)); }

__device__ __forceinline__ unsigned ldcg_u32(const unsigned* p) {
    unsigned v;
    asm volatile("ld.global.cg.u32 %0, [%1];" : "=r"(v) : "l"(p));
    return v;
}

// grid barrier
__device__ __forceinline__ void grid_bar(unsigned* local_phase) {
    __syncthreads();
    unsigned target = ++(*local_phase);
    if (threadIdx.x == 0) {
        __threadfence();
        unsigned old = atomicAdd(&g_bar, 1);
        if (old == GRID - 1) {
            atomicExch(&g_bar, 0);
            atomicAdd(&g_phase, 1);
        } else {
            while (ldcg_u32(&g_phase) < target) { __nanosleep(40); }
        }
        __threadfence();
    }
    __syncthreads();
}

// ---------------- init ----------------
__global__ void init_kernel(const float* __restrict__ b_ih1, const float* __restrict__ b_hh1) {
    int i = blockIdx.x * blockDim.x + threadIdx.x;
    if (i < Tdim * 2048) {
        g_hcath[0][i] = __float2half(0.f);
        g_hcath[1][i] = __float2half(0.f);
    }
    if (i < Tdim * Hdim) { g_c0[i] = 0.f; g_c1[i] = 0.f; }
    if (i < G4) g_bias1[i] = b_ih1[i] + b_hh1[i];
    if (i == 0) { g_bar = 0; g_phase = 0; }
}

// generic fp32 -> fp16 convert (8 elements/thread)
__global__ void f2h(const float* __restrict__ src, __half* __restrict__ dst) {
    size_t i = ((size_t)blockIdx.x * blockDim.x + threadIdx.x) * 8;
    float4 v0 = *reinterpret_cast<const float4*>(src + i);
    float4 v1 = *reinterpret_cast<const float4*>(src + i + 4);
    uint4 h;
    h.x = pack2(v0.x, v0.y); h.y = pack2(v0.z, v0.w);
    h.z = pack2(v1.x, v1.y); h.w = pack2(v1.z, v1.w);
    *reinterpret_cast<uint4*>(dst + i) = h;
}

// g_W1h = fp16([W_ih1 | W_hh1]) : [4096][2048]
__global__ void make_w1cat(const float* __restrict__ Wi1, const float* __restrict__ Wh1) {
    size_t i = (size_t)blockIdx.x * 256 + threadIdx.x;   // float4 index; 2M total
    int n = (int)(i >> 9);
    int c4 = (int)(i & 511);
    const float4* src = (c4 < 256)
        ? reinterpret_cast<const float4*>(Wi1 + (size_t)n * Hdim) + c4
        : reinterpret_cast<const float4*>(Wh1 + (size_t)n * Hdim) + (c4 - 256);
    float4 v = *src;
    uint2 h;
    h.x = pack2(v.x, v.y); h.y = pack2(v.z, v.w);
    *reinterpret_cast<uint2*>(g_W1h + i * 4) = h;
}

// ---------------- build X (fp16) ----------------
__global__ void build_x(const float* __restrict__ features, const int* __restrict__ captions,
                        const float* __restrict__ embW) {
    int b = blockIdx.x, t = blockIdx.y;
    const float* src = (t == 0) ? (features + (size_t)b * Edim)
                                : (embW + (size_t)captions[b * Tdim + t] * Edim);
    float4 v = reinterpret_cast<const float4*>(src)[threadIdx.x];
    uint2 h;
    h.x = pack2(v.x, v.y); h.y = pack2(v.z, v.w);
    reinterpret_cast<uint2*>(g_Xh + ((size_t)b * Tdim + t) * Edim)[threadIdx.x] = h;
}

// ---------------- big fp16 GEMM: C[M,N] = A[M,K] @ W[N,K]^T + bias ----------------
// K counted in halves; chunk = 64 halves = 32 u32 words per row.
#define BM 128
#define BN 256

__global__ void __launch_bounds__(256, 1) gemm_f16(
    const __half* __restrict__ A, const __half* __restrict__ W,
    const float* __restrict__ bias0, const float* __restrict__ bias1,
    float* __restrict__ C, int M, int N, int K)
{
    extern __shared__ uint32_t smw[];
    uint32_t* As = smw;                    // [2][BM][36] words
    uint32_t* Bs = smw + 2 * BM * LDSS;    // [2][BN][36] words

    int tid = threadIdx.x;
    int lane = tid & 31, warp = tid >> 5;
    int m0 = blockIdx.x * BM, n0 = blockIdx.y * BN;
    int wm = (warp >> 2) * 64, wn = (warp & 3) * 64;

    float acc[4][8][4];
    #pragma unroll
    for (int a = 0; a < 4; a++)
        #pragma unroll
        for (int b = 0; b < 8; b++)
            #pragma unroll
            for (int c = 0; c < 4; c++) acc[a][b][c] = 0.f;

    auto load_stage = [&](int s, int buf) {
        int k0 = s * 64;   // halves
        const __half* Ag = A + (size_t)m0 * K + k0;
        #pragma unroll
        for (int i = 0; i < 4; i++) {
            int idx = tid + i * 256;
            int m = idx >> 3, seg = idx & 7;
            cp16(&As[(buf * BM + m) * LDSS + seg * 4], Ag + (size_t)m * K + seg * 8);
        }
        const __half* Wg = W + (size_t)n0 * K + k0;
        #pragma unroll
        for (int i = 0; i < 8; i++) {
            int idx = tid + i * 256;
            int n = idx >> 3, seg = idx & 7;
            cp16(&Bs[(buf * BN + n) * LDSS + seg * 4], Wg + (size_t)n * K + seg * 8);
        }
        cp_commit();
    };

    int S = K / 64;
    load_stage(0, 0);
    for (int s = 0; s < S; s++) {
        int buf = s & 1;
        if (s + 1 < S) {
            load_stage(s + 1, buf ^ 1);
            asm volatile("cp.async.wait_group 1;" ::: "memory");
        } else {
            asm volatile("cp.async.wait_group 0;" ::: "memory");
        }
        __syncthreads();
        const uint32_t* Ab = &As[buf * BM * LDSS];
        const uint32_t* Bb = &Bs[buf * BN * LDSS];
        #pragma unroll
        for (int kc = 0; kc < 4; kc++) {   // each kc = 16 halves = 8 words
            int c0 = kc * 8 + (lane & 3);
            uint32_t af[4][4];
            #pragma unroll
            for (int mt = 0; mt < 4; mt++) {
                int r = wm + mt * 16 + (lane >> 2);
                af[mt][0] = Ab[r * LDSS + c0];
                af[mt][1] = Ab[(r + 8) * LDSS + c0];
                af[mt][2] = Ab[r * LDSS + c0 + 4];
                af[mt][3] = Ab[(r + 8) * LDSS + c0 + 4];
            }
            #pragma unroll
            for (int nt = 0; nt < 8; nt++) {
                int n = wn + nt * 8 + (lane >> 2);
                uint32_t bf[2] = { Bb[n * LDSS + c0], Bb[n * LDSS + c0 + 4] };
                #pragma unroll
                for (int mt = 0; mt < 4; mt++) mma_f16(acc[mt][nt], af[mt], bf);
            }
        }
        __syncthreads();
    }

    #pragma unroll
    for (int nt = 0; nt < 8; nt++) {
        int col = n0 + wn + nt * 8 + 2 * (lane & 3);
        float bv0 = bias0[col], bv1 = bias0[col + 1];
        if (bias1) { bv0 += bias1[col]; bv1 += bias1[col + 1]; }
        #pragma unroll
        for (int mt = 0; mt < 4; mt++) {
            int row = m0 + wm + mt * 16 + (lane >> 2);
            float2 v;
            v.x = acc[mt][nt][0] + bv0; v.y = acc[mt][nt][1] + bv1;
            *reinterpret_cast<float2*>(C + (size_t)row * N + col) = v;
            v.x = acc[mt][nt][2] + bv0; v.y = acc[mt][nt][3] + bv1;
            *reinterpret_cast<float2*>(C + (size_t)(row + 8) * N + col) = v;
        }
    }
}

// ---------------- persistent recurrence kernel (fp16 operands) ----------------
// 144 blocks (1/SM), 512 threads = 16 warps.
// Blocks 0..47  : layer0  jt = b/3, ks = b%3, K=1024 halves (16 chunks: 6/5/5)
// Blocks 48..143: layer1  jt = lb/6, ks = lb%6, K=2048 halves (32 chunks: 6,6,5,5,5,5)
__global__ void __launch_bounds__(512, 1) recurrence_kernel()
{
    extern __shared__ uint32_t smw[];
    uint32_t* As = smw;                    // [2][32][36] words
    uint32_t* Ws = smw + 2 * 32 * LDSS;    // [2][256][36] words

    int bid = blockIdx.x;
    int tid = threadIdx.x, lane = tid & 31, warp = tid >> 5;
    int layer = (bid >= 48) ? 1 : 0;
    int jt, ks, cstart, ccnt, tstart, tcnt;
    if (!layer) {
        jt = bid / 3; ks = bid % 3;
        cstart = (ks == 0) ? 0 : 6 + (ks - 1) * 5;
        ccnt = (ks == 0) ? 6 : 5;                              // 16 chunks total
        tstart = ks * 11; tcnt = (ks == 2) ? 10 : 11;          // epilogue t-split
    } else {
        int lb = bid - 48;
        jt = lb / 6; ks = lb % 6;
        cstart = (ks < 2) ? ks * 6 : 12 + (ks - 2) * 5;        // 32 chunks total
        ccnt = (ks < 2) ? 6 : 5;
        tstart = (ks < 4) ? ks * 6 : 24 + (ks - 4) * 4;
        tcnt = (ks < 4) ? 6 : 4;
    }
    const __half* W = layer ? g_W1h : g_W0h;
    int wstride = layer ? 2048 : 1024;     // halves
    float* gpart = layer ? g_part1 : g_part0;

    unsigned local_phase = 0;

    for (int s = 0; s <= Bdim; s++) {
        int par = s & 1;
        bool active = layer ? (s >= 1) : (s < Bdim);

        if (active) {
            const __half* A = g_hcath[par];

            float acc[2][2][4];
            #pragma unroll
            for (int nt = 0; nt < 2; nt++)
                #pragma unroll
                for (int m = 0; m < 2; m++)
                    #pragma unroll
                    for (int c = 0; c < 4; c++) acc[nt][m][c] = 0.f;

            auto load = [&](int c, int buf) {
                int kw = c * 64;   // halves
                if (tid < 256) {
                    int row = tid >> 3, seg = tid & 7;
                    cp16(&As[(buf * 32 + row) * LDSS + seg * 4],
                         A + row * 2048 + kw + seg * 8);
                }
                #pragma unroll
                for (int i = 0; i < 4; i++) {
                    int idx = tid + i * 512;
                    int wr = idx >> 3, seg = idx & 7;
                    int grow = (wr >> 6) * 1024 + jt * 64 + (wr & 63);
                    cp16(&Ws[(buf * 256 + wr) * LDSS + seg * 4],
                         W + (size_t)grow * wstride + kw + seg * 8);
                }
                cp_commit();
            };

            load(cstart, 0);
            for (int cc = 0; cc < ccnt; cc++) {
                int buf = cc & 1;
                if (cc + 1 < ccnt) {
                    load(cstart + cc + 1, buf ^ 1);
                    asm volatile("cp.async.wait_group 1;" ::: "memory");
                } else {
                    asm volatile("cp.async.wait_group 0;" ::: "memory");
                }
                __syncthreads();
                const uint32_t* Ab = As + buf * 32 * LDSS;
                const uint32_t* Wb = Ws + buf * 256 * LDSS;
                int r = lane >> 2;
                #pragma unroll
                for (int kc = 0; kc < 4; kc++) {
                    int c0 = kc * 8 + (lane & 3);
                    uint32_t af[2][4];
                    #pragma unroll
                    for (int m = 0; m < 2; m++) {
                        af[m][0] = Ab[(m * 16 + r) * LDSS + c0];
                        af[m][1] = Ab[(m * 16 + r + 8) * LDSS + c0];
                        af[m][2] = Ab[(m * 16 + r) * LDSS + c0 + 4];
                        af[m][3] = Ab[(m * 16 + r + 8) * LDSS + c0 + 4];
                    }
                    #pragma unroll
                    for (int nt = 0; nt < 2; nt++) {
                        int srow = warp * 16 + nt * 8 + r;
                        uint32_t bf[2] = { Wb[srow * LDSS + c0], Wb[srow * LDSS + c0 + 4] };
                        mma_f16(acc[nt][0], af[0], bf);
                        mma_f16(acc[nt][1], af[1], bf);
                    }
                }
                __syncthreads();
            }

            // store partials to fixed slots
            #pragma unroll
            for (int nt = 0; nt < 2; nt++) {
                int col = (warp >> 2) * 1024 + jt * 64 + (warp & 3) * 16 + nt * 8 + 2 * (lane & 3);
                #pragma unroll
                for (int m = 0; m < 2; m++) {
                    int row = m * 16 + (lane >> 2);
                    *reinterpret_cast<float2*>(gpart + ((size_t)(ks * 32 + row) * G4 + col)) =
                        make_float2(acc[nt][m][0], acc[nt][m][1]);
                    *reinterpret_cast<float2*>(gpart + ((size_t)(ks * 32 + row + 8) * G4 + col)) =
                        make_float2(acc[nt][m][2], acc[nt][m][3]);
                }
            }
        }

        grid_bar(&local_phase);

        // ---- distributed epilogue (fixed-order reduce, deterministic) ----
        __half* hout = g_hcath[par ^ 1];
        if (!layer) {
            if (s < Bdim) {
                int elems = tcnt * 64;
                #pragma unroll
                for (int i = 0; i < 2; i++) {
                    int idx = tid + i * 512;
                    if (idx < elems) {
                        int t = tstart + (idx >> 6), j = jt * 64 + (idx & 63);
                        float sg[4];
                        #pragma unroll
                        for (int g = 0; g < 4; g++) {
                            sg[g] = __ldcg(g_part0 + ((size_t)(0 * 32 + t) * G4 + g * 1024 + j))
                                  + __ldcg(g_part0 + ((size_t)(1 * 32 + t) * G4 + g * 1024 + j))
                                  + __ldcg(g_part0 + ((size_t)(2 * 32 + t) * G4 + g * 1024 + j))
                                  + g_G0[((size_t)s * 32 + t) * G4 + g * 1024 + j];
                        }
                        float cn = sigm(sg[1]) * g_c0[t * Hdim + j] + sigm(sg[0]) * tanhf(sg[2]);
                        float hn = sigm(sg[3]) * tanhf(cn);
                        g_c0[t * Hdim + j] = cn;
                        hout[t * 2048 + j] = __float2half(hn);
                    }
                }
            }
        } else {
            if (s >= 1) {
                int elems = tcnt * 64;
                int idx = tid;
                if (idx < elems) {
                    int t = tstart + (idx >> 6), j = jt * 64 + (idx & 63);
                    float sg[4];
                    #pragma unroll
                    for (int g = 0; g < 4; g++) {
                        float ssum = g_bias1[g * 1024 + j];
                        #pragma unroll
                        for (int k = 0; k < 6; k++)
                            ssum += __ldcg(g_part1 + ((size_t)(k * 32 + t) * G4 + g * 1024 + j));
                        sg[g] = ssum;
                    }
                    float cn = sigm(sg[1]) * g_c1[t * Hdim + j] + sigm(sg[0]) * tanhf(sg[2]);
                    float hn = sigm(sg[3]) * tanhf(cn);
                    g_c1[t * Hdim + j] = cn;
                    __half hr = __float2half(hn);
                    hout[t * 2048 + 1024 + j] = hr;
                    g_ysh[((size_t)(s - 1) * 32 + t) * Hdim + j] = hr;
                }
            }
        }

        grid_bar(&local_phase);
    }
}

// ---------------- launch ----------------
extern "C" void kernel_launch(void* const* d_in, const int* in_sizes, int n_in,
                              void* d_out, int out_size)
{
    const float* features = (const float*)d_in[0];
    const int*   captions = (const int*)d_in[1];
    const float* embed_W  = (const float*)d_in[2];
    const float* W_ih0    = (const float*)d_in[3];
    const float* W_hh0    = (const float*)d_in[4];
    const float* b_ih0    = (const float*)d_in[5];
    const float* b_hh0    = (const float*)d_in[6];
    const float* W_ih1    = (const float*)d_in[7];
    const float* W_hh1    = (const float*)d_in[8];
    const float* b_ih1    = (const float*)d_in[9];
    const float* b_hh1    = (const float*)d_in[10];
    const float* fc_W     = (const float*)d_in[11];
    const float* fc_b     = (const float*)d_in[12];
    float* out = (float*)d_out;

    void *pXh = nullptr, *pG0 = nullptr, *pysh = nullptr;
    void *pW0h = nullptr, *pWih0h = nullptr, *pfcWh = nullptr;
    cudaGetSymbolAddress(&pXh, g_Xh);
    cudaGetSymbolAddress(&pG0, g_G0);
    cudaGetSymbolAddress(&pysh, g_ysh);
    cudaGetSymbolAddress(&pW0h, g_W0h);
    cudaGetSymbolAddress(&pWih0h, g_Wih0h);
    cudaGetSymbolAddress(&pfcWh, g_fcWh);

    size_t smem_gemm = (size_t)(2 * (BM + BN) * LDSS) * sizeof(uint32_t);   // ~108 KB
    cudaFuncSetAttribute(gemm_f16, cudaFuncAttributeMaxDynamicSharedMemorySize, (int)smem_gemm);
    size_t smem_step = (size_t)(2 * (32 + 256) * LDSS) * sizeof(uint32_t);  // ~83 KB
    cudaFuncSetAttribute(recurrence_kernel, cudaFuncAttributeMaxDynamicSharedMemorySize, (int)smem_step);

    init_kernel<<<(Tdim * 2048 + 255) / 256, 256>>>(b_ih1, b_hh1);
    f2h<<<2048, 256>>>(W_hh0, (__half*)pW0h);            // 4M elems
    f2h<<<1024, 256>>>(W_ih0, (__half*)pWih0h);          // 2M elems
    f2h<<<16000, 256>>>(fc_W, (__half*)pfcWh);           // 32.77M elems
    make_w1cat<<<8192, 256>>>(W_ih1, W_hh1);
    build_x<<<dim3(Bdim, Tdim), 128>>>(features, captions, embed_W);

    // G0 = X @ W_ih0^T + b_ih0 + b_hh0   (M=4096, N=4096, K=512)
    gemm_f16<<<dim3(G4 / BM, G4 / BN), 256, smem_gemm>>>(
        (const __half*)pXh, (const __half*)pWih0h, b_ih0, b_hh0,
        (float*)pG0, Bdim * Tdim, G4, Edim);

    // persistent recurrence: all 129 fused steps in one launch
    recurrence_kernel<<<GRID, 512, smem_step>>>();

    // logits = ys @ fc_W^T + fc_b   (M=4096, N=32000, K=1024)
    gemm_f16<<<dim3((Bdim * Tdim) / BM, Vdim / BN), 256, smem_gemm>>>(
        (const __half*)pysh, (const __half*)pfcWh, fc_b, nullptr,
        out, Bdim * Tdim, Vdim, Hdim);
}

// round 12
// speedup vs baseline: 2.8054x; 1.0883x over previous
#include <cuda_runtime.h>
#include <cuda_fp16.h>
#include <cstdint>
#include <math.h>

#define Bdim 128
#define Tdim 32
#define Edim 512
#define Hdim 1024
#define G4   4096
#define Vdim 32000
#define GRID 144
#define LDSS 36    // gemm_f16 SMEM row stride (words)
#define RWPAD 180  // recurrence SMEM row stride (words); 180%32=20 -> conflict-free

// ---------------- device scratch ----------------
__device__ __align__(16) __half g_Xh[Bdim * Tdim * Edim];          // 4 MB
__device__ __align__(16) float  g_G0[Bdim * Tdim * G4];            // 64 MB
__device__ __align__(16) __half g_ysh[Bdim * Tdim * Hdim];         // 8 MB
__device__ __align__(16) float  g_bias1[G4];
__device__ __align__(16) __half g_hcath[2][Tdim * 2048];           // [par][t][h0|h1]
__device__ __align__(16) float  g_c0[Tdim * Hdim];
__device__ __align__(16) float  g_c1[Tdim * Hdim];
__device__ __align__(16) __half g_W0h[(size_t)G4 * 1024];          // fp16(W_hh0) 8MB
__device__ __align__(16) __half g_W1h[(size_t)G4 * 2048];          // fp16([Wih1|Whh1]) 16MB
__device__ __align__(16) __half g_Wih0h[(size_t)G4 * 512];         // fp16(W_ih0) 4MB
__device__ __align__(16) __half g_fcWh[(size_t)Vdim * 1024];       // fp16(fc_W) 64MB
__device__ __align__(16) float  g_part0[3 * Tdim * G4];            // 1.5MB
__device__ __align__(16) float  g_part1[6 * Tdim * G4];            // 3MB
__device__ int g_cnt[2][16];
__device__ unsigned g_bar;
__device__ unsigned g_phase;

// ---------------- helpers ----------------
__device__ __forceinline__ uint32_t pack2(float a, float b) {
    __half2 h = __floats2half2_rn(a, b);
    return *reinterpret_cast<uint32_t*>(&h);
}

__device__ __forceinline__ void mma_f16(float c[4], const uint32_t a[4], const uint32_t b[2]) {
    asm volatile(
        "mma.sync.aligned.m16n8k16.row.col.f32.f16.f16.f32 "
        "{%0,%1,%2,%3}, {%4,%5,%6,%7}, {%8,%9}, {%0,%1,%2,%3};"
        : "+f"(c[0]), "+f"(c[1]), "+f"(c[2]), "+f"(c[3])
        : "r"(a[0]), "r"(a[1]), "r"(a[2]), "r"(a[3]), "r"(b[0]), "r"(b[1]));
}

__device__ __forceinline__ void cp16(void* s, const void* g) {
    uint32_t sa = (uint32_t)__cvta_generic_to_shared(s);
    asm volatile("cp.async.cg.shared.global [%0], [%1], 16;" :: "r"(sa), "l"(g));
}
__device__ __forceinline__ void cp_commit() { asm volatile("cp.async.commit_group;" ::: "memory"); }

__device__ __forceinline__ float sigm(float x) { return 1.f / (1.f + expf(-x)); }

__device__ __forceinline__ unsigned ldcg_u32(const unsigned* p) {
    unsigned v;
    asm volatile("ld.global.cg.u32 %0, [%1];" : "=r"(v) : "l"(p));
    return v;
}

// grid barrier
__device__ __forceinline__ void grid_bar(unsigned* local_phase) {
    __syncthreads();
    unsigned target = ++(*local_phase);
    if (threadIdx.x == 0) {
        __threadfence();
        unsigned old = atomicAdd(&g_bar, 1);
        if (old == GRID - 1) {
            atomicExch(&g_bar, 0);
            atomicAdd(&g_phase, 1);
        } else {
            while (ldcg_u32(&g_phase) < target) { __nanosleep(40); }
        }
        __threadfence();
    }
    __syncthreads();
}

// ---------------- init ----------------
__global__ void init_kernel(const float* __restrict__ b_ih1, const float* __restrict__ b_hh1) {
    int i = blockIdx.x * blockDim.x + threadIdx.x;
    if (i < Tdim * 2048) {
        g_hcath[0][i] = __float2half(0.f);
        g_hcath[1][i] = __float2half(0.f);
    }
    if (i < Tdim * Hdim) { g_c0[i] = 0.f; g_c1[i] = 0.f; }
    if (i < G4) g_bias1[i] = b_ih1[i] + b_hh1[i];
    if (i < 16) { g_cnt[0][i] = 0; g_cnt[1][i] = 0; }
    if (i == 0) { g_bar = 0; g_phase = 0; }
}

// generic fp32 -> fp16 convert (8 elements/thread)
__global__ void f2h(const float* __restrict__ src, __half* __restrict__ dst) {
    size_t i = ((size_t)blockIdx.x * blockDim.x + threadIdx.x) * 8;
    float4 v0 = *reinterpret_cast<const float4*>(src + i);
    float4 v1 = *reinterpret_cast<const float4*>(src + i + 4);
    uint4 h;
    h.x = pack2(v0.x, v0.y); h.y = pack2(v0.z, v0.w);
    h.z = pack2(v1.x, v1.y); h.w = pack2(v1.z, v1.w);
    *reinterpret_cast<uint4*>(dst + i) = h;
}

// g_W1h = fp16([W_ih1 | W_hh1]) : [4096][2048]
__global__ void make_w1cat(const float* __restrict__ Wi1, const float* __restrict__ Wh1) {
    size_t i = (size_t)blockIdx.x * 256 + threadIdx.x;   // float4 index; 2M total
    int n = (int)(i >> 9);
    int c4 = (int)(i & 511);
    const float4* src = (c4 < 256)
        ? reinterpret_cast<const float4*>(Wi1 + (size_t)n * Hdim) + c4
        : reinterpret_cast<const float4*>(Wh1 + (size_t)n * Hdim) + (c4 - 256);
    float4 v = *src;
    uint2 h;
    h.x = pack2(v.x, v.y); h.y = pack2(v.z, v.w);
    *reinterpret_cast<uint2*>(g_W1h + i * 4) = h;
}

// ---------------- build X (fp16) ----------------
__global__ void build_x(const float* __restrict__ features, const int* __restrict__ captions,
                        const float* __restrict__ embW) {
    int b = blockIdx.x, t = blockIdx.y;
    const float* src = (t == 0) ? (features + (size_t)b * Edim)
                                : (embW + (size_t)captions[b * Tdim + t] * Edim);
    float4 v = reinterpret_cast<const float4*>(src)[threadIdx.x];
    uint2 h;
    h.x = pack2(v.x, v.y); h.y = pack2(v.z, v.w);
    reinterpret_cast<uint2*>(g_Xh + ((size_t)b * Tdim + t) * Edim)[threadIdx.x] = h;
}

// ---------------- big fp16 GEMM: C[M,N] = A[M,K] @ W[N,K]^T + bias ----------------
#define BM 128
#define BN 256

__global__ void __launch_bounds__(256, 1) gemm_f16(
    const __half* __restrict__ A, const __half* __restrict__ W,
    const float* __restrict__ bias0, const float* __restrict__ bias1,
    float* __restrict__ C, int M, int N, int K)
{
    extern __shared__ uint32_t smw[];
    uint32_t* As = smw;                    // [2][BM][36] words
    uint32_t* Bs = smw + 2 * BM * LDSS;    // [2][BN][36] words

    int tid = threadIdx.x;
    int lane = tid & 31, warp = tid >> 5;
    int m0 = blockIdx.x * BM, n0 = blockIdx.y * BN;
    int wm = (warp >> 2) * 64, wn = (warp & 3) * 64;

    float acc[4][8][4];
    #pragma unroll
    for (int a = 0; a < 4; a++)
        #pragma unroll
        for (int b = 0; b < 8; b++)
            #pragma unroll
            for (int c = 0; c < 4; c++) acc[a][b][c] = 0.f;

    auto load_stage = [&](int s, int buf) {
        int k0 = s * 64;   // halves
        const __half* Ag = A + (size_t)m0 * K + k0;
        #pragma unroll
        for (int i = 0; i < 4; i++) {
            int idx = tid + i * 256;
            int m = idx >> 3, seg = idx & 7;
            cp16(&As[(buf * BM + m) * LDSS + seg * 4], Ag + (size_t)m * K + seg * 8);
        }
        const __half* Wg = W + (size_t)n0 * K + k0;
        #pragma unroll
        for (int i = 0; i < 8; i++) {
            int idx = tid + i * 256;
            int n = idx >> 3, seg = idx & 7;
            cp16(&Bs[(buf * BN + n) * LDSS + seg * 4], Wg + (size_t)n * K + seg * 8);
        }
        cp_commit();
    };

    int S = K / 64;
    load_stage(0, 0);
    for (int s = 0; s < S; s++) {
        int buf = s & 1;
        if (s + 1 < S) {
            load_stage(s + 1, buf ^ 1);
            asm volatile("cp.async.wait_group 1;" ::: "memory");
        } else {
            asm volatile("cp.async.wait_group 0;" ::: "memory");
        }
        __syncthreads();
        const uint32_t* Ab = &As[buf * BM * LDSS];
        const uint32_t* Bb = &Bs[buf * BN * LDSS];
        #pragma unroll
        for (int kc = 0; kc < 4; kc++) {   // each kc = 16 halves = 8 words
            int c0 = kc * 8 + (lane & 3);
            uint32_t af[4][4];
            #pragma unroll
            for (int mt = 0; mt < 4; mt++) {
                int r = wm + mt * 16 + (lane >> 2);
                af[mt][0] = Ab[r * LDSS + c0];
                af[mt][1] = Ab[(r + 8) * LDSS + c0];
                af[mt][2] = Ab[r * LDSS + c0 + 4];
                af[mt][3] = Ab[(r + 8) * LDSS + c0 + 4];
            }
            #pragma unroll
            for (int nt = 0; nt < 8; nt++) {
                int n = wn + nt * 8 + (lane >> 2);
                uint32_t bf[2] = { Bb[n * LDSS + c0], Bb[n * LDSS + c0 + 4] };
                #pragma unroll
                for (int mt = 0; mt < 4; mt++) mma_f16(acc[mt][nt], af[mt], bf);
            }
        }
        __syncthreads();
    }

    #pragma unroll
    for (int nt = 0; nt < 8; nt++) {
        int col = n0 + wn + nt * 8 + 2 * (lane & 3);
        float bv0 = bias0[col], bv1 = bias0[col + 1];
        if (bias1) { bv0 += bias1[col]; bv1 += bias1[col + 1]; }
        #pragma unroll
        for (int mt = 0; mt < 4; mt++) {
            int row = m0 + wm + mt * 16 + (lane >> 2);
            float2 v;
            v.x = acc[mt][nt][0] + bv0; v.y = acc[mt][nt][1] + bv1;
            *reinterpret_cast<float2*>(C + (size_t)row * N + col) = v;
            v.x = acc[mt][nt][2] + bv0; v.y = acc[mt][nt][3] + bv1;
            *reinterpret_cast<float2*>(C + (size_t)(row + 8) * N + col) = v;
        }
    }
}

// ---------------- persistent recurrence kernel: weights SMEM-resident ----------------
// 144 blocks (1/SM), 512 threads = 16 warps.
// Blocks 0..47  : layer0  jt = b/3, ks = b%3  (K=1024: widths 352/336/336)
// Blocks 48..143: layer1  jt = lb/6, ks = lb%6 (K=2048: widths 352,352,336x4)
// Each block keeps its [256 x cw] weight slice in SMEM for all 129 steps.
// Per step: cp.async A-slice -> HMMA -> partial STG -> per-tile counter; the
// LAST k-slice block of each tile runs the fused LSTM epilogue; ONE grid barrier.
__global__ void __launch_bounds__(512, 1) recurrence_kernel()
{
    extern __shared__ uint32_t smw[];
    uint32_t* Ws = smw;                  // [256][RWPAD] words
    uint32_t* As = smw + 256 * RWPAD;    // [32][RWPAD] words

    int bid = blockIdx.x;
    int tid = threadIdx.x, lane = tid & 31, warp = tid >> 5;
    int layer = (bid >= 48) ? 1 : 0;
    int jt, ks, KS, cstart, cw;
    if (!layer) {
        jt = bid / 3; ks = bid % 3; KS = 3;
        cstart = (ks == 0) ? 0 : 352 + (ks - 1) * 336;
        cw = (ks == 0) ? 352 : 336;
    } else {
        int lb = bid - 48;
        jt = lb / 6; ks = lb % 6; KS = 6;
        cstart = (ks < 2) ? ks * 352 : 704 + (ks - 2) * 336;
        cw = (ks < 2) ? 352 : 336;
    }
    const __half* W = layer ? g_W1h : g_W0h;
    int wstride = layer ? 2048 : 1024;     // halves
    float* gpart = layer ? g_part1 : g_part0;
    int cw8 = cw >> 3;     // 16B chunks per row
    int kcnt = cw >> 4;    // k-groups of 16 halves

    // ---- one-time weight slice load ----
    for (int idx = tid; idx < 256 * cw8; idx += 512) {
        int wr = idx / cw8, seg = idx - wr * cw8;
        int grow = (wr >> 6) * 1024 + jt * 64 + (wr & 63);
        cp16(&Ws[wr * RWPAD + seg * 4], W + (size_t)grow * wstride + cstart + seg * 8);
    }
    cp_commit();
    asm volatile("cp.async.wait_group 0;" ::: "memory");
    __syncthreads();

    unsigned local_phase = 0;
    __shared__ int doEpi;

    for (int s = 0; s <= Bdim; s++) {
        int par = s & 1;
        bool active = layer ? (s >= 1) : (s < Bdim);

        if (active) {
            const __half* A = g_hcath[par];

            // load A slice [32][cw]
            for (int idx = tid; idx < 32 * cw8; idx += 512) {
                int row = idx / cw8, seg = idx - row * cw8;
                cp16(&As[row * RWPAD + seg * 4], A + row * 2048 + cstart + seg * 8);
            }
            cp_commit();
            asm volatile("cp.async.wait_group 0;" ::: "memory");
            __syncthreads();

            float acc[2][2][4];
            #pragma unroll
            for (int nt = 0; nt < 2; nt++)
                #pragma unroll
                for (int m = 0; m < 2; m++)
                    #pragma unroll
                    for (int c = 0; c < 4; c++) acc[nt][m][c] = 0.f;

            int r = lane >> 2;
            for (int kc = 0; kc < kcnt; kc++) {
                int c0 = kc * 8 + (lane & 3);
                uint32_t af[2][4];
                #pragma unroll
                for (int m = 0; m < 2; m++) {
                    af[m][0] = As[(m * 16 + r) * RWPAD + c0];
                    af[m][1] = As[(m * 16 + r + 8) * RWPAD + c0];
                    af[m][2] = As[(m * 16 + r) * RWPAD + c0 + 4];
                    af[m][3] = As[(m * 16 + r + 8) * RWPAD + c0 + 4];
                }
                #pragma unroll
                for (int nt = 0; nt < 2; nt++) {
                    int srow = warp * 16 + nt * 8 + r;
                    uint32_t bf[2] = { Ws[srow * RWPAD + c0], Ws[srow * RWPAD + c0 + 4] };
                    mma_f16(acc[nt][0], af[0], bf);
                    mma_f16(acc[nt][1], af[1], bf);
                }
            }

            // store partials to fixed slots
            #pragma unroll
            for (int nt = 0; nt < 2; nt++) {
                int col = (warp >> 2) * 1024 + jt * 64 + (warp & 3) * 16 + nt * 8 + 2 * (lane & 3);
                #pragma unroll
                for (int m = 0; m < 2; m++) {
                    int row = m * 16 + (lane >> 2);
                    *reinterpret_cast<float2*>(gpart + ((size_t)(ks * 32 + row) * G4 + col)) =
                        make_float2(acc[nt][m][0], acc[nt][m][1]);
                    *reinterpret_cast<float2*>(gpart + ((size_t)(ks * 32 + row + 8) * G4 + col)) =
                        make_float2(acc[nt][m][2], acc[nt][m][3]);
                }
            }
            __threadfence();
            __syncthreads();
            if (tid == 0) {
                int old = atomicAdd(&g_cnt[layer][jt], 1);
                doEpi = (old == KS - 1) ? 1 : 0;
                if (doEpi) atomicExch(&g_cnt[layer][jt], 0);
            }
            __syncthreads();

            if (doEpi) {
                __threadfence();   // acquire other blocks' partials
                __half* hout = g_hcath[par ^ 1];
                if (!layer) {
                    #pragma unroll
                    for (int i = 0; i < 4; i++) {
                        int idx = tid + i * 512;
                        int t = idx >> 6, j = jt * 64 + (idx & 63);
                        float sg[4];
                        #pragma unroll
                        for (int g = 0; g < 4; g++) {
                            float ssum = g_G0[((size_t)s * 32 + t) * G4 + g * 1024 + j];
                            #pragma unroll
                            for (int k = 0; k < 3; k++)
                                ssum += __ldcg(g_part0 + ((size_t)(k * 32 + t) * G4 + g * 1024 + j));
                            sg[g] = ssum;
                        }
                        float cn = sigm(sg[1]) * g_c0[t * Hdim + j] + sigm(sg[0]) * tanhf(sg[2]);
                        float hn = sigm(sg[3]) * tanhf(cn);
                        g_c0[t * Hdim + j] = cn;
                        hout[t * 2048 + j] = __float2half(hn);
                    }
                } else {
                    #pragma unroll
                    for (int i = 0; i < 4; i++) {
                        int idx = tid + i * 512;
                        int t = idx >> 6, j = jt * 64 + (idx & 63);
                        float sg[4];
                        #pragma unroll
                        for (int g = 0; g < 4; g++) {
                            float ssum = g_bias1[g * 1024 + j];
                            #pragma unroll
                            for (int k = 0; k < 6; k++)
                                ssum += __ldcg(g_part1 + ((size_t)(k * 32 + t) * G4 + g * 1024 + j));
                            sg[g] = ssum;
                        }
                        float cn = sigm(sg[1]) * g_c1[t * Hdim + j] + sigm(sg[0]) * tanhf(sg[2]);
                        float hn = sigm(sg[3]) * tanhf(cn);
                        g_c1[t * Hdim + j] = cn;
                        __half hr = __float2half(hn);
                        hout[t * 2048 + 1024 + j] = hr;
                        g_ysh[((size_t)(s - 1) * 32 + t) * Hdim + j] = hr;
                    }
                }
            }
        }

        grid_bar(&local_phase);
    }
}

// ---------------- launch ----------------
extern "C" void kernel_launch(void* const* d_in, const int* in_sizes, int n_in,
                              void* d_out, int out_size)
{
    const float* features = (const float*)d_in[0];
    const int*   captions = (const int*)d_in[1];
    const float* embed_W  = (const float*)d_in[2];
    const float* W_ih0    = (const float*)d_in[3];
    const float* W_hh0    = (const float*)d_in[4];
    const float* b_ih0    = (const float*)d_in[5];
    const float* b_hh0    = (const float*)d_in[6];
    const float* W_ih1    = (const float*)d_in[7];
    const float* W_hh1    = (const float*)d_in[8];
    const float* b_ih1    = (const float*)d_in[9];
    const float* b_hh1    = (const float*)d_in[10];
    const float* fc_W     = (const float*)d_in[11];
    const float* fc_b     = (const float*)d_in[12];
    float* out = (float*)d_out;

    void *pXh = nullptr, *pG0 = nullptr, *pysh = nullptr;
    void *pW0h = nullptr, *pWih0h = nullptr, *pfcWh = nullptr;
    cudaGetSymbolAddress(&pXh, g_Xh);
    cudaGetSymbolAddress(&pG0, g_G0);
    cudaGetSymbolAddress(&pysh, g_ysh);
    cudaGetSymbolAddress(&pW0h, g_W0h);
    cudaGetSymbolAddress(&pWih0h, g_Wih0h);
    cudaGetSymbolAddress(&pfcWh, g_fcWh);

    size_t smem_gemm = (size_t)(2 * (BM + BN) * LDSS) * sizeof(uint32_t);   // ~108 KB
    cudaFuncSetAttribute(gemm_f16, cudaFuncAttributeMaxDynamicSharedMemorySize, (int)smem_gemm);
    size_t smem_rec = (size_t)((256 + 32) * RWPAD) * sizeof(uint32_t);      // 207,360 B
    cudaFuncSetAttribute(recurrence_kernel, cudaFuncAttributeMaxDynamicSharedMemorySize, (int)smem_rec);

    init_kernel<<<(Tdim * 2048 + 255) / 256, 256>>>(b_ih1, b_hh1);
    f2h<<<2048, 256>>>(W_hh0, (__half*)pW0h);            // 4M elems
    f2h<<<1024, 256>>>(W_ih0, (__half*)pWih0h);          // 2M elems
    f2h<<<16000, 256>>>(fc_W, (__half*)pfcWh);           // 32.77M elems
    make_w1cat<<<8192, 256>>>(W_ih1, W_hh1);
    build_x<<<dim3(Bdim, Tdim), 128>>>(features, captions, embed_W);

    // G0 = X @ W_ih0^T + b_ih0 + b_hh0   (M=4096, N=4096, K=512)
    gemm_f16<<<dim3(G4 / BM, G4 / BN), 256, smem_gemm>>>(
        (const __half*)pXh, (const __half*)pWih0h, b_ih0, b_hh0,
        (float*)pG0, Bdim * Tdim, G4, Edim);

    // persistent recurrence: all 129 fused steps, weights SMEM-resident
    recurrence_kernel<<<GRID, 512, smem_rec>>>();

    // logits = ys @ fc_W^T + fc_b   (M=4096, N=32000, K=1024)
    gemm_f16<<<dim3((Bdim * Tdim) / BM, Vdim / BN), 256, smem_gemm>>>(
        (const __half*)pysh, (const __half*)pfcWh, fc_b, nullptr,
        out, Bdim * Tdim, Vdim, Hdim);
}